// round 2
// baseline (speedup 1.0000x reference)
#include <cuda_runtime.h>
#include <math.h>

#define Bq 4
#define Tt 8
#define TQn 9
#define HWc 1024
#define Dm 256
#define NHh 8
#define MLPD 1024
#define ROWS_SP (Bq*Tt*HWc)   /* 32768 */
#define ROWS_T  (Bq*TQn*HWc)  /* 36864 */

// ---------------- scratch (static device globals; no runtime alloc) ----------------
__device__ float g_ln  [(size_t)ROWS_T * Dm];
__device__ float g_qkv [(size_t)ROWS_T * 768];
__device__ float g_ao  [(size_t)ROWS_T * Dm];
__device__ float g_tmp [(size_t)ROWS_SP * Dm];
__device__ float g_x   [(size_t)ROWS_T * Dm];
__device__ float g_x2  [(size_t)ROWS_T * Dm];
__device__ float g_h   [(size_t)ROWS_T * MLPD];
__device__ float g_wqkv[Dm * 768];
__device__ float g_bqkv[768];

// ---------------- small helpers ----------------
__device__ __forceinline__ float wsum(float v) {
#pragma unroll
    for (int o = 16; o; o >>= 1) v += __shfl_xor_sync(0xffffffffu, v, o);
    return v;
}

// ---------------- pack [Wq|Wk|Wv] -> (256,768), biases -> (768) ----------------
__global__ void pack_qkv(const float* __restrict__ wq, const float* __restrict__ wk,
                         const float* __restrict__ wv, const float* __restrict__ bq,
                         const float* __restrict__ bk, const float* __restrict__ bv)
{
    int i = blockIdx.x * 256 + threadIdx.x;
    if (i < Dm * 768) {
        int k = i / 768, n = i % 768;
        float v;
        if (n < 256)       v = wq[k * 256 + n];
        else if (n < 512)  v = wk[k * 256 + n - 256];
        else               v = wv[k * 256 + n - 512];
        g_wqkv[i] = v;
        if (i < 768)
            g_bqkv[i] = (i < 256) ? bq[i] : (i < 512) ? bk[i - 256] : bv[i - 512];
    }
}

// ---------------- LayerNorm: warp per row of 256; optional row remap ----------------
// src_row = row + (row/grp)*skip  (spatial: grp=8192, skip=1024 skips frame 8 per batch)
__global__ void ln_kernel(const float* __restrict__ X, const float* __restrict__ gam,
                          const float* __restrict__ bet, float* __restrict__ Y,
                          int nrows, int grp, int skip)
{
    int row = blockIdx.x * 4 + (threadIdx.x >> 5);
    if (row >= nrows) return;
    int l = threadIdx.x & 31;
    size_t src = ((size_t)row + (size_t)(row / grp) * skip) * Dm;
    float4 v0 = *(const float4*)(X + src + 4 * l);
    float4 v1 = *(const float4*)(X + src + 128 + 4 * l);
    float s  = v0.x + v0.y + v0.z + v0.w + v1.x + v1.y + v1.z + v1.w;
    float sq = v0.x*v0.x + v0.y*v0.y + v0.z*v0.z + v0.w*v0.w
             + v1.x*v1.x + v1.y*v1.y + v1.z*v1.z + v1.w*v1.w;
    s = wsum(s); sq = wsum(sq);
    float mean = s * (1.f / 256.f);
    float var  = sq * (1.f / 256.f) - mean * mean;
    float rstd = rsqrtf(var + 1e-5f);
    float4 ga0 = *(const float4*)(gam + 4 * l), ga1 = *(const float4*)(gam + 128 + 4 * l);
    float4 be0 = *(const float4*)(bet + 4 * l), be1 = *(const float4*)(bet + 128 + 4 * l);
    float4 o0, o1;
    o0.x = (v0.x - mean) * rstd * ga0.x + be0.x;
    o0.y = (v0.y - mean) * rstd * ga0.y + be0.y;
    o0.z = (v0.z - mean) * rstd * ga0.z + be0.z;
    o0.w = (v0.w - mean) * rstd * ga0.w + be0.w;
    o1.x = (v1.x - mean) * rstd * ga1.x + be1.x;
    o1.y = (v1.y - mean) * rstd * ga1.y + be1.y;
    o1.z = (v1.z - mean) * rstd * ga1.z + be1.z;
    o1.w = (v1.w - mean) * rstd * ga1.w + be1.w;
    *(float4*)(Y + (size_t)row * Dm + 4 * l)       = o0;
    *(float4*)(Y + (size_t)row * Dm + 128 + 4 * l) = o1;
}

// ---------------- SGEMM 128x128x8, 256 threads, 8x8/thread ----------------
// C[M,N] = A[M,K] @ B[K,N] + bias[N]  (+ res[M,N])  (gelu)
// epi bit0: residual add, bit1: exact gelu
__global__ __launch_bounds__(256) void sgemm_k(
    const float* __restrict__ A, const float* __restrict__ Bw,
    const float* __restrict__ bias, const float* __restrict__ res,
    float* __restrict__ C, int M, int N, int K, int epi)
{
    __shared__ float As[8][128];
    __shared__ float Bs[8][128];
    int tid = threadIdx.x;
    int bx = blockIdx.x, by = blockIdx.y;
    const float* Ab = A + (size_t)by * 128 * K;
    const float* Bb = Bw + bx * 128;
    int arow = tid >> 1, acol = (tid & 1) * 4;
    int brow = tid >> 5, bcol = (tid & 31) * 4;
    int ty = (tid >> 4) * 8, tx = (tid & 15) * 8;
    float acc[8][8];
#pragma unroll
    for (int i = 0; i < 8; i++)
#pragma unroll
        for (int j = 0; j < 8; j++) acc[i][j] = 0.f;

    for (int k0 = 0; k0 < K; k0 += 8) {
        float4 av = *(const float4*)(Ab + (size_t)arow * K + k0 + acol);
        As[acol + 0][arow] = av.x;
        As[acol + 1][arow] = av.y;
        As[acol + 2][arow] = av.z;
        As[acol + 3][arow] = av.w;
        *(float4*)(&Bs[brow][bcol]) = *(const float4*)(Bb + (size_t)(k0 + brow) * N + bcol);
        __syncthreads();
#pragma unroll
        for (int kk = 0; kk < 8; kk++) {
            float a[8], bb[8];
            *(float4*)(a)      = *(const float4*)(&As[kk][ty]);
            *(float4*)(a + 4)  = *(const float4*)(&As[kk][ty + 4]);
            *(float4*)(bb)     = *(const float4*)(&Bs[kk][tx]);
            *(float4*)(bb + 4) = *(const float4*)(&Bs[kk][tx + 4]);
#pragma unroll
            for (int i = 0; i < 8; i++)
#pragma unroll
                for (int j = 0; j < 8; j++)
                    acc[i][j] = fmaf(a[i], bb[j], acc[i][j]);
        }
        __syncthreads();
    }
#pragma unroll
    for (int i = 0; i < 8; i++) {
        size_t row  = (size_t)by * 128 + ty + i;
        size_t base = row * N + bx * 128 + tx;
#pragma unroll
        for (int j = 0; j < 8; j++) {
            float v = acc[i][j] + bias[bx * 128 + tx + j];
            if (epi & 1) v += res[base + j];
            if (epi & 2) v = 0.5f * v * (1.0f + erff(v * 0.7071067811865476f));
            C[base + j] = v;
        }
    }
}

// ---------------- spatial 3x3 windowed attention: block=token, warp=head ----------------
__global__ void spatial_attn()
{
    int r = blockIdx.x;                 // 0..32767 : (b*8+t)*1024 + hw
    int h = threadIdx.x >> 5;
    int l = threadIdx.x & 31;
    int bt = r >> 10, n = r & 1023;
    int y = n >> 5, x = n & 31;
    const float scale = 0.17677669529663687f; // 1/sqrt(32)

    float q = g_qkv[(size_t)r * 768 + h * 32 + l];
    float sc[9], vv[9];
    bool  ok[9];
#pragma unroll
    for (int kk = 0; kk < 9; kk++) {
        int ny = y + kk / 3 - 1, nx = x + kk % 3 - 1;
        bool v = ((unsigned)ny < 32u) && ((unsigned)nx < 32u);
        ok[kk] = v;
        int rn = v ? ((bt << 10) + (ny << 5) + nx) : r;
        const float* kp = g_qkv + (size_t)rn * 768 + 256 + h * 32;
        float kvv = kp[l];
        vv[kk] = kp[256 + l];           // V lives 256 floats after K
        float d = wsum(q * kvv) * scale;
        sc[kk] = v ? d : -1e30f;
    }
    float m = sc[0];
#pragma unroll
    for (int kk = 1; kk < 9; kk++) m = fmaxf(m, sc[kk]);
    float den = 0.f, o = 0.f;
#pragma unroll
    for (int kk = 0; kk < 9; kk++) {
        float e = ok[kk] ? __expf(sc[kk] - m) : 0.f;
        den += e;
        o += e * vv[kk];
    }
    g_ao[(size_t)r * 256 + h * 32 + l] = o / den;
}

// ---------------- assemble x = [spatial_out + residual ; last frame] ----------------
__global__ void assemble_x(const float* __restrict__ query)
{
    size_t i = (size_t)blockIdx.x * 256 + threadIdx.x;  // over ROWS_T*256
    size_t row = i >> 8;            // (b*9+t)*1024 + hw
    int bt9 = (int)(row >> 10);
    int t = bt9 % 9, b = bt9 / 9;
    float qv = query[i];
    if (t < 8) {
        size_t sprow = ((size_t)(b * 8 + t) << 10) + (row & 1023);
        g_x[i] = g_tmp[sprow * 256 + (i & 255)] + qv;
    } else {
        g_x[i] = qv;
    }
}

// ---------------- temporal RoPE attention: block=sequence(b,hw), warp=head ----------------
__global__ void temporal_attn(const unsigned char* __restrict__ tmask)
{
    int s = blockIdx.x;             // 0..4095 : b*1024 + hw
    int h = threadIdx.x >> 5;
    int l = threadIdx.x & 31;
    int b = s >> 10, hw = s & 1023;
    const float scale = 0.17677669529663687f;

    float inv = __powf(10000.f, -(float)(2 * (l & 15)) / 32.f);
    float q[9], k[9], v[9];
#pragma unroll
    for (int t = 0; t < 9; t++) {
        size_t base = ((size_t)(b * 9 + t) * 1024 + hw) * 768 + h * 32;
        float qv = g_qkv[base + l];
        float kv = g_qkv[base + 256 + l];
        v[t]     = g_qkv[base + 512 + l];
        float c, sn;
        sincosf((float)t * inv, &sn, &c);
        float qp = __shfl_xor_sync(0xffffffffu, qv, 16);
        float kp = __shfl_xor_sync(0xffffffffu, kv, 16);
        q[t] = (l < 16) ? (qv * c - qp * sn) : (qp * sn + qv * c);
        k[t] = (l < 16) ? (kv * c - kp * sn) : (kp * sn + kv * c);
    }
#pragma unroll
    for (int tq = 0; tq < 9; tq++) {
        float scr[9];
        float m = -1e30f;
#pragma unroll
        for (int tk = 0; tk < 9; tk++) {
            float d = wsum(q[tq] * k[tk]) * scale;
            if (tmask[tq * 9 + tk]) d = -1e9f;
            scr[tk] = d;
            m = fmaxf(m, d);
        }
        float den = 0.f, o = 0.f;
#pragma unroll
        for (int tk = 0; tk < 9; tk++) {
            float e = __expf(scr[tk] - m);
            den += e;
            o += e * v[tk];
        }
        size_t orow = (size_t)(b * 9 + tq) * 1024 + hw;
        g_ao[orow * 256 + h * 32 + l] = o / den;
    }
}

// ---------------- CLS frame spatial mean + broadcast (on g_x2, t=0) ----------------
__global__ void cls_avg()
{
    int b = blockIdx.x;            // 0..3
    int d = blockIdx.y * 32 + (threadIdx.x & 31);
    int part = threadIdx.x >> 5;   // 0..7
    float s = 0.f;
    for (int hw = part; hw < 1024; hw += 8)
        s += g_x2[(((size_t)b * 9) * 1024 + hw) * 256 + d];
    __shared__ float sm[8][32];
    sm[part][threadIdx.x & 31] = s;
    __syncthreads();
    if (part == 0) {
        float tot = 0.f;
#pragma unroll
        for (int p = 0; p < 8; p++) tot += sm[p][threadIdx.x & 31];
        sm[0][threadIdx.x & 31] = tot * (1.f / 1024.f);
    }
    __syncthreads();
    float avg = sm[0][threadIdx.x & 31];
    for (int hw = part; hw < 1024; hw += 8)
        g_x2[(((size_t)b * 9) * 1024 + hw) * 256 + d] = avg;
}

// ---------------- launch ----------------
extern "C" void kernel_launch(void* const* d_in, const int* in_sizes, int n_in,
                              void* d_out, int out_size)
{
    const float* query = (const float*)d_in[0];
    const unsigned char* tmask = (const unsigned char*)d_in[2];
    const float* sln_g = (const float*)d_in[3];
    const float* sln_b = (const float*)d_in[4];
    const float* s_wq = (const float*)d_in[5];
    const float* s_bq = (const float*)d_in[6];
    const float* s_wk = (const float*)d_in[7];
    const float* s_bk = (const float*)d_in[8];
    const float* s_wv = (const float*)d_in[9];
    const float* s_bv = (const float*)d_in[10];
    const float* s_wo = (const float*)d_in[11];
    const float* s_bo = (const float*)d_in[12];
    const float* tln_g = (const float*)d_in[13];
    const float* tln_b = (const float*)d_in[14];
    const float* t_wq = (const float*)d_in[15];
    const float* t_bq = (const float*)d_in[16];
    const float* t_wk = (const float*)d_in[17];
    const float* t_bk = (const float*)d_in[18];
    const float* t_wv = (const float*)d_in[19];
    const float* t_bv = (const float*)d_in[20];
    const float* t_wo = (const float*)d_in[21];
    const float* t_bo = (const float*)d_in[22];
    const float* mln_g = (const float*)d_in[23];
    const float* mln_b = (const float*)d_in[24];
    const float* w1 = (const float*)d_in[25];
    const float* b1 = (const float*)d_in[26];
    const float* w2 = (const float*)d_in[27];
    const float* b2 = (const float*)d_in[28];
    float* out = (float*)d_out;

    float *p_ln, *p_qkv, *p_ao, *p_tmp, *p_x, *p_x2, *p_h, *p_wqkv, *p_bqkv;
    cudaGetSymbolAddress((void**)&p_ln, g_ln);
    cudaGetSymbolAddress((void**)&p_qkv, g_qkv);
    cudaGetSymbolAddress((void**)&p_ao, g_ao);
    cudaGetSymbolAddress((void**)&p_tmp, g_tmp);
    cudaGetSymbolAddress((void**)&p_x, g_x);
    cudaGetSymbolAddress((void**)&p_x2, g_x2);
    cudaGetSymbolAddress((void**)&p_h, g_h);
    cudaGetSymbolAddress((void**)&p_wqkv, g_wqkv);
    cudaGetSymbolAddress((void**)&p_bqkv, g_bqkv);

    // ---- spatial stage ----
    pack_qkv<<<768, 256>>>(s_wq, s_wk, s_wv, s_bq, s_bk, s_bv);
    ln_kernel<<<ROWS_SP / 4, 128>>>(query, sln_g, sln_b, p_ln, ROWS_SP, 8192, 1024);
    sgemm_k<<<dim3(6, ROWS_SP / 128), 256>>>(p_ln, p_wqkv, p_bqkv, nullptr, p_qkv,
                                             ROWS_SP, 768, 256, 0);
    spatial_attn<<<ROWS_SP, 256>>>();
    sgemm_k<<<dim3(2, ROWS_SP / 128), 256>>>(p_ao, s_wo, s_bo, nullptr, p_tmp,
                                             ROWS_SP, 256, 256, 0);
    assemble_x<<<ROWS_T, 256>>>(query);

    // ---- temporal stage ----
    ln_kernel<<<ROWS_T / 4, 128>>>(p_x, tln_g, tln_b, p_ln, ROWS_T, 1 << 30, 0);
    pack_qkv<<<768, 256>>>(t_wq, t_wk, t_wv, t_bq, t_bk, t_bv);
    sgemm_k<<<dim3(6, ROWS_T / 128), 256>>>(p_ln, p_wqkv, p_bqkv, nullptr, p_qkv,
                                            ROWS_T, 768, 256, 0);
    temporal_attn<<<Bq * HWc, 256>>>(tmask);
    sgemm_k<<<dim3(2, ROWS_T / 128), 256>>>(p_ao, t_wo, t_bo, p_x, p_x2,
                                            ROWS_T, 256, 256, 1);
    cls_avg<<<dim3(4, 8), 256>>>();

    // ---- MLP stage ----
    ln_kernel<<<ROWS_T / 4, 128>>>(p_x2, mln_g, mln_b, p_ln, ROWS_T, 1 << 30, 0);
    sgemm_k<<<dim3(8, ROWS_T / 128), 256>>>(p_ln, w1, b1, nullptr, p_h,
                                            ROWS_T, MLPD, 256, 2);
    sgemm_k<<<dim3(2, ROWS_T / 128), 256>>>(p_h, w2, b2, p_x2, out,
                                            ROWS_T, 256, MLPD, 1);
}

// round 4
// speedup vs baseline: 2.2616x; 2.2616x over previous
#include <cuda_runtime.h>
#include <math.h>
#include <stdint.h>

#define Bq 4
#define Tt 8
#define TQn 9
#define HWc 1024
#define Dm 256
#define MLPD 1024
#define ROWS_SP (Bq*Tt*HWc)   /* 32768 */
#define ROWS_T  (Bq*TQn*HWc)  /* 36864 */

// ---------------- scratch (static device globals) ----------------
__device__ float g_ln  [(size_t)ROWS_T * Dm];
__device__ float g_qkv [(size_t)ROWS_T * 768];
__device__ float g_ao  [(size_t)ROWS_T * Dm];
__device__ float g_tmp [(size_t)ROWS_SP * Dm];
__device__ float g_x   [(size_t)ROWS_T * Dm];
__device__ float g_x2  [(size_t)ROWS_T * Dm];
__device__ float g_h   [(size_t)ROWS_T * MLPD];
__device__ float g_wqkvT[768 * 256];      // [N=768, K=256]
__device__ float g_bqkv[768];
__device__ float g_wT1[256 * 256];        // s_wo^T  [N,K]
__device__ float g_wT2[256 * 256];        // t_wo^T  [N,K]
__device__ float g_w1T[1024 * 256];       // w1^T    [N=1024,K=256]
__device__ float g_w2T[256 * 1024];       // w2^T    [N=256, K=1024]

// ---------------- helpers ----------------
__device__ __forceinline__ float wsum(float v) {
#pragma unroll
    for (int o = 16; o; o >>= 1) v += __shfl_xor_sync(0xffffffffu, v, o);
    return v;
}
__device__ __forceinline__ uint32_t smem_u32(const void* p) {
    uint32_t a;
    asm("{ .reg .u64 t; cvta.to.shared.u64 t, %1; cvt.u32.u64 %0, t; }" : "=r"(a) : "l"(p));
    return a;
}
#define CP_ASYNC16(dst, src) \
    asm volatile("cp.async.cg.shared.global [%0], [%1], 16;" :: "r"(dst), "l"(src))
#define CP_COMMIT() asm volatile("cp.async.commit_group;")
#define CP_WAIT0()  asm volatile("cp.async.wait_group 0;")

__device__ __forceinline__ void mma_tf32(float* c, const uint32_t* a, const uint32_t* b) {
    asm volatile(
        "mma.sync.aligned.m16n8k8.row.col.f32.tf32.tf32.f32 "
        "{%0,%1,%2,%3}, {%4,%5,%6,%7}, {%8,%9}, {%0,%1,%2,%3};"
        : "+f"(c[0]), "+f"(c[1]), "+f"(c[2]), "+f"(c[3])
        : "r"(a[0]), "r"(a[1]), "r"(a[2]), "r"(a[3]), "r"(b[0]), "r"(b[1]));
}

// ---------------- weight packing / transpose ----------------
__global__ void pack_qkvT(const float* __restrict__ wq, const float* __restrict__ wk,
                          const float* __restrict__ wv, const float* __restrict__ bq,
                          const float* __restrict__ bk, const float* __restrict__ bv)
{
    int i = blockIdx.x * 256 + threadIdx.x;      // over 768*256
    if (i < 768 * 256) {
        int n = i >> 8, k = i & 255;
        const float* w = (n < 256) ? wq : (n < 512) ? wk : wv;
        int col = n & 255;
        g_wqkvT[i] = w[k * 256 + col];
        if (i < 768)
            g_bqkv[i] = (i < 256) ? bq[i] : (i < 512) ? bk[i - 256] : bv[i - 512];
    }
}

__global__ void transpose_w(const float* __restrict__ in, float* __restrict__ out,
                            int Kd, int Nd)
{
    int i = blockIdx.x * 256 + threadIdx.x;
    if (i < Kd * Nd) {
        int n = i / Kd, k = i % Kd;
        out[i] = in[k * Nd + n];
    }
}

// ---------------- LayerNorm (warp/row, optional row remap) ----------------
__global__ void ln_kernel(const float* __restrict__ X, const float* __restrict__ gam,
                          const float* __restrict__ bet, float* __restrict__ Y,
                          int nrows, int grp, int skip)
{
    int row = blockIdx.x * 4 + (threadIdx.x >> 5);
    if (row >= nrows) return;
    int l = threadIdx.x & 31;
    size_t src = ((size_t)row + (size_t)(row / grp) * skip) * Dm;
    float4 v0 = *(const float4*)(X + src + 4 * l);
    float4 v1 = *(const float4*)(X + src + 128 + 4 * l);
    float s  = v0.x + v0.y + v0.z + v0.w + v1.x + v1.y + v1.z + v1.w;
    float sq = v0.x*v0.x + v0.y*v0.y + v0.z*v0.z + v0.w*v0.w
             + v1.x*v1.x + v1.y*v1.y + v1.z*v1.z + v1.w*v1.w;
    s = wsum(s); sq = wsum(sq);
    float mean = s * (1.f / 256.f);
    float var  = sq * (1.f / 256.f) - mean * mean;
    float rstd = rsqrtf(var + 1e-5f);
    float4 ga0 = *(const float4*)(gam + 4 * l), ga1 = *(const float4*)(gam + 128 + 4 * l);
    float4 be0 = *(const float4*)(bet + 4 * l), be1 = *(const float4*)(bet + 128 + 4 * l);
    float4 o0, o1;
    o0.x = (v0.x - mean) * rstd * ga0.x + be0.x;
    o0.y = (v0.y - mean) * rstd * ga0.y + be0.y;
    o0.z = (v0.z - mean) * rstd * ga0.z + be0.z;
    o0.w = (v0.w - mean) * rstd * ga0.w + be0.w;
    o1.x = (v1.x - mean) * rstd * ga1.x + be1.x;
    o1.y = (v1.y - mean) * rstd * ga1.y + be1.y;
    o1.z = (v1.z - mean) * rstd * ga1.z + be1.z;
    o1.w = (v1.w - mean) * rstd * ga1.w + be1.w;
    *(float4*)(Y + (size_t)row * Dm + 4 * l)       = o0;
    *(float4*)(Y + (size_t)row * Dm + 128 + 4 * l) = o1;
}

// ---------------- tf32 mma.sync GEMM: CTA 128x128, warp 64x32, K chunks of 32 ----------------
// C[M,N] = A[M,K] @ B[K,N] + bias ; BT is B^T in [N,K] row-major.
// epi bit0: residual add, bit1: exact gelu
#define TSTRIDE 36                    /* padded floats per smem row */
#define TILEF   (128 * TSTRIDE)       /* floats per tile buffer */
#define GSMEM_BYTES (4 * TILEF * 4)   /* 2 bufs x (A,B) */

__global__ __launch_bounds__(256) void mma_gemm(
    const float* __restrict__ A, const float* __restrict__ BT,
    const float* __restrict__ bias, const float* __restrict__ res,
    float* __restrict__ C, int M, int N, int K, int epi)
{
    extern __shared__ float smem[];
    float* bufA[2] = { smem,             smem + 2 * TILEF };
    float* bufB[2] = { smem + TILEF,     smem + 3 * TILEF };
    uint32_t sA[2] = { smem_u32(bufA[0]), smem_u32(bufA[1]) };
    uint32_t sB[2] = { smem_u32(bufB[0]), smem_u32(bufB[1]) };

    int tid = threadIdx.x;
    int wid = tid >> 5, lane = tid & 31;
    int wm = wid >> 2, wn = wid & 3;           // warp grid 2 x 4
    int gid = lane >> 2, tig = lane & 3;
    int bx = blockIdx.x, by = blockIdx.y;

    const float* Abase = A  + (size_t)(by * 128) * K;
    const float* Bbase = BT + (size_t)(bx * 128) * K;
    int nch = K >> 5;

    float acc[4][4][4];
#pragma unroll
    for (int i = 0; i < 4; i++)
#pragma unroll
        for (int j = 0; j < 4; j++)
#pragma unroll
            for (int c = 0; c < 4; c++) acc[i][j][c] = 0.f;

    // preload chunk 0
    {
#pragma unroll
        for (int i = 0; i < 4; i++) {
            int idx = i * 256 + tid, row = idx >> 3, c4 = idx & 7;
            CP_ASYNC16(sA[0] + row * (TSTRIDE * 4) + c4 * 16, Abase + (size_t)row * K + c4 * 4);
            CP_ASYNC16(sB[0] + row * (TSTRIDE * 4) + c4 * 16, Bbase + (size_t)row * K + c4 * 4);
        }
        CP_COMMIT();
    }

    for (int ch = 0; ch < nch; ch++) {
        int b = ch & 1;
        CP_WAIT0();
        __syncthreads();
        if (ch + 1 < nch) {
            const float* Ag = Abase + (ch + 1) * 32;
            const float* Bg = Bbase + (ch + 1) * 32;
#pragma unroll
            for (int i = 0; i < 4; i++) {
                int idx = i * 256 + tid, row = idx >> 3, c4 = idx & 7;
                CP_ASYNC16(sA[b ^ 1] + row * (TSTRIDE * 4) + c4 * 16, Ag + (size_t)row * K + c4 * 4);
                CP_ASYNC16(sB[b ^ 1] + row * (TSTRIDE * 4) + c4 * 16, Bg + (size_t)row * K + c4 * 4);
            }
            CP_COMMIT();
        }
        const float* Ab = bufA[b];
        const float* Bb = bufB[b];
#pragma unroll
        for (int k0 = 0; k0 < 32; k0 += 8) {
            uint32_t af[4][4], bf[4][2];
#pragma unroll
            for (int mt = 0; mt < 4; mt++) {
                const float* p = Ab + (wm * 64 + mt * 16 + gid) * TSTRIDE + k0 + tig;
                af[mt][0] = __float_as_uint(p[0]);
                af[mt][1] = __float_as_uint(p[8 * TSTRIDE]);
                af[mt][2] = __float_as_uint(p[4]);
                af[mt][3] = __float_as_uint(p[8 * TSTRIDE + 4]);
            }
#pragma unroll
            for (int nt = 0; nt < 4; nt++) {
                const float* p = Bb + (wn * 32 + nt * 8 + gid) * TSTRIDE + k0 + tig;
                bf[nt][0] = __float_as_uint(p[0]);
                bf[nt][1] = __float_as_uint(p[4]);
            }
#pragma unroll
            for (int mt = 0; mt < 4; mt++)
#pragma unroll
                for (int nt = 0; nt < 4; nt++)
                    mma_tf32(acc[mt][nt], af[mt], bf[nt]);
        }
        __syncthreads();
    }

    // ---- epilogue ----
#pragma unroll
    for (int mt = 0; mt < 4; mt++) {
#pragma unroll
        for (int half = 0; half < 2; half++) {
            size_t row = (size_t)(by * 128 + wm * 64 + mt * 16 + gid + half * 8);
#pragma unroll
            for (int nt = 0; nt < 4; nt++) {
                int cc = bx * 128 + wn * 32 + nt * 8 + 2 * tig;
                float2 v;
                v.x = acc[mt][nt][2 * half + 0] + bias[cc];
                v.y = acc[mt][nt][2 * half + 1] + bias[cc + 1];
                size_t base = row * N + cc;
                if (epi & 1) {
                    float2 rr = *(const float2*)(res + base);
                    v.x += rr.x; v.y += rr.y;
                }
                if (epi & 2) {
                    v.x = 0.5f * v.x * (1.0f + erff(v.x * 0.7071067811865476f));
                    v.y = 0.5f * v.y * (1.0f + erff(v.y * 0.7071067811865476f));
                }
                *(float2*)(C + base) = v;
            }
        }
    }
}

// ---------------- spatial 3x3 windowed attention ----------------
__global__ void spatial_attn()
{
    int r = blockIdx.x;
    int h = threadIdx.x >> 5;
    int l = threadIdx.x & 31;
    int bt = r >> 10, n = r & 1023;
    int y = n >> 5, x = n & 31;
    const float scale = 0.17677669529663687f;

    float q = g_qkv[(size_t)r * 768 + h * 32 + l];
    float sc[9], vv[9];
    bool  ok[9];
#pragma unroll
    for (int kk = 0; kk < 9; kk++) {
        int ny = y + kk / 3 - 1, nx = x + kk % 3 - 1;
        bool v = ((unsigned)ny < 32u) && ((unsigned)nx < 32u);
        ok[kk] = v;
        int rn = v ? ((bt << 10) + (ny << 5) + nx) : r;
        const float* kp = g_qkv + (size_t)rn * 768 + 256 + h * 32;
        float kvv = kp[l];
        vv[kk] = kp[256 + l];
        float d = wsum(q * kvv) * scale;
        sc[kk] = v ? d : -1e30f;
    }
    float m = sc[0];
#pragma unroll
    for (int kk = 1; kk < 9; kk++) m = fmaxf(m, sc[kk]);
    float den = 0.f, o = 0.f;
#pragma unroll
    for (int kk = 0; kk < 9; kk++) {
        float e = ok[kk] ? __expf(sc[kk] - m) : 0.f;
        den += e;
        o += e * vv[kk];
    }
    g_ao[(size_t)r * 256 + h * 32 + l] = o / den;
}

// ---------------- assemble x = [spatial_out + residual ; last frame] ----------------
__global__ void assemble_x(const float* __restrict__ query)
{
    size_t i = (size_t)blockIdx.x * 256 + threadIdx.x;
    size_t row = i >> 8;
    int bt9 = (int)(row >> 10);
    int t = bt9 % 9, b = bt9 / 9;
    float qv = query[i];
    if (t < 8) {
        size_t sprow = ((size_t)(b * 8 + t) << 10) + (row & 1023);
        g_x[i] = g_tmp[sprow * 256 + (i & 255)] + qv;
    } else {
        g_x[i] = qv;
    }
}

// ---------------- temporal RoPE attention ----------------
__global__ void temporal_attn(const unsigned char* __restrict__ tmask)
{
    int s = blockIdx.x;
    int h = threadIdx.x >> 5;
    int l = threadIdx.x & 31;
    int b = s >> 10, hw = s & 1023;
    const float scale = 0.17677669529663687f;

    float inv = __powf(10000.f, -(float)(2 * (l & 15)) / 32.f);
    float q[9], k[9], v[9];
#pragma unroll
    for (int t = 0; t < 9; t++) {
        size_t base = ((size_t)(b * 9 + t) * 1024 + hw) * 768 + h * 32;
        float qv = g_qkv[base + l];
        float kv = g_qkv[base + 256 + l];
        v[t]     = g_qkv[base + 512 + l];
        float c, sn;
        sincosf((float)t * inv, &sn, &c);
        float qp = __shfl_xor_sync(0xffffffffu, qv, 16);
        float kp = __shfl_xor_sync(0xffffffffu, kv, 16);
        q[t] = (l < 16) ? (qv * c - qp * sn) : (qp * sn + qv * c);
        k[t] = (l < 16) ? (kv * c - kp * sn) : (kp * sn + kv * c);
    }
#pragma unroll
    for (int tq = 0; tq < 9; tq++) {
        float scr[9];
        float m = -1e30f;
#pragma unroll
        for (int tk = 0; tk < 9; tk++) {
            float d = wsum(q[tq] * k[tk]) * scale;
            if (tmask[tq * 9 + tk]) d = -1e9f;
            scr[tk] = d;
            m = fmaxf(m, d);
        }
        float den = 0.f, o = 0.f;
#pragma unroll
        for (int tk = 0; tk < 9; tk++) {
            float e = __expf(scr[tk] - m);
            den += e;
            o += e * v[tk];
        }
        size_t orow = (size_t)(b * 9 + tq) * 1024 + hw;
        g_ao[orow * 256 + h * 32 + l] = o / den;
    }
}

// ---------------- CLS frame spatial mean + broadcast ----------------
__global__ void cls_avg()
{
    int b = blockIdx.x;
    int d = blockIdx.y * 32 + (threadIdx.x & 31);
    int part = threadIdx.x >> 5;
    float s = 0.f;
    for (int hw = part; hw < 1024; hw += 8)
        s += g_x2[(((size_t)b * 9) * 1024 + hw) * 256 + d];
    __shared__ float sm[8][32];
    sm[part][threadIdx.x & 31] = s;
    __syncthreads();
    if (part == 0) {
        float tot = 0.f;
#pragma unroll
        for (int p = 0; p < 8; p++) tot += sm[p][threadIdx.x & 31];
        sm[0][threadIdx.x & 31] = tot * (1.f / 1024.f);
    }
    __syncthreads();
    float avg = sm[0][threadIdx.x & 31];
    for (int hw = part; hw < 1024; hw += 8)
        g_x2[(((size_t)b * 9) * 1024 + hw) * 256 + d] = avg;
}

// ---------------- launch ----------------
extern "C" void kernel_launch(void* const* d_in, const int* in_sizes, int n_in,
                              void* d_out, int out_size)
{
    const float* query = (const float*)d_in[0];
    const unsigned char* tmask = (const unsigned char*)d_in[2];
    const float* sln_g = (const float*)d_in[3];
    const float* sln_b = (const float*)d_in[4];
    const float* s_wq = (const float*)d_in[5];
    const float* s_bq = (const float*)d_in[6];
    const float* s_wk = (const float*)d_in[7];
    const float* s_bk = (const float*)d_in[8];
    const float* s_wv = (const float*)d_in[9];
    const float* s_bv = (const float*)d_in[10];
    const float* s_wo = (const float*)d_in[11];
    const float* s_bo = (const float*)d_in[12];
    const float* tln_g = (const float*)d_in[13];
    const float* tln_b = (const float*)d_in[14];
    const float* t_wq = (const float*)d_in[15];
    const float* t_bq = (const float*)d_in[16];
    const float* t_wk = (const float*)d_in[17];
    const float* t_bk = (const float*)d_in[18];
    const float* t_wv = (const float*)d_in[19];
    const float* t_bv = (const float*)d_in[20];
    const float* t_wo = (const float*)d_in[21];
    const float* t_bo = (const float*)d_in[22];
    const float* mln_g = (const float*)d_in[23];
    const float* mln_b = (const float*)d_in[24];
    const float* w1 = (const float*)d_in[25];
    const float* b1 = (const float*)d_in[26];
    const float* w2 = (const float*)d_in[27];
    const float* b2 = (const float*)d_in[28];
    float* out = (float*)d_out;

    float *p_ln, *p_qkv, *p_ao, *p_tmp, *p_x, *p_x2, *p_h;
    float *p_wqkvT, *p_bqkv, *p_wT1, *p_wT2, *p_w1T, *p_w2T;
    cudaGetSymbolAddress((void**)&p_ln, g_ln);
    cudaGetSymbolAddress((void**)&p_qkv, g_qkv);
    cudaGetSymbolAddress((void**)&p_ao, g_ao);
    cudaGetSymbolAddress((void**)&p_tmp, g_tmp);
    cudaGetSymbolAddress((void**)&p_x, g_x);
    cudaGetSymbolAddress((void**)&p_x2, g_x2);
    cudaGetSymbolAddress((void**)&p_h, g_h);
    cudaGetSymbolAddress((void**)&p_wqkvT, g_wqkvT);
    cudaGetSymbolAddress((void**)&p_bqkv, g_bqkv);
    cudaGetSymbolAddress((void**)&p_wT1, g_wT1);
    cudaGetSymbolAddress((void**)&p_wT2, g_wT2);
    cudaGetSymbolAddress((void**)&p_w1T, g_w1T);
    cudaGetSymbolAddress((void**)&p_w2T, g_w2T);

    cudaFuncSetAttribute(mma_gemm, cudaFuncAttributeMaxDynamicSharedMemorySize, GSMEM_BYTES);

    // ---- weight prep ----
    pack_qkvT<<<768, 256>>>(s_wq, s_wk, s_wv, s_bq, s_bk, s_bv);
    transpose_w<<<256, 256>>>(s_wo, p_wT1, 256, 256);
    transpose_w<<<256, 256>>>(t_wo, p_wT2, 256, 256);
    transpose_w<<<1024, 256>>>(w1, p_w1T, 256, 1024);
    transpose_w<<<1024, 256>>>(w2, p_w2T, 1024, 256);

    // ---- spatial stage ----
    ln_kernel<<<ROWS_SP / 4, 128>>>(query, sln_g, sln_b, p_ln, ROWS_SP, 8192, 1024);
    mma_gemm<<<dim3(6, ROWS_SP / 128), 256, GSMEM_BYTES>>>(p_ln, p_wqkvT, p_bqkv, nullptr,
                                                           p_qkv, ROWS_SP, 768, 256, 0);
    spatial_attn<<<ROWS_SP, 256>>>();
    mma_gemm<<<dim3(2, ROWS_SP / 128), 256, GSMEM_BYTES>>>(p_ao, p_wT1, s_bo, nullptr,
                                                           p_tmp, ROWS_SP, 256, 256, 0);
    assemble_x<<<ROWS_T, 256>>>(query);

    // ---- temporal stage ----
    ln_kernel<<<ROWS_T / 4, 128>>>(p_x, tln_g, tln_b, p_ln, ROWS_T, 1 << 30, 0);
    pack_qkvT<<<768, 256>>>(t_wq, t_wk, t_wv, t_bq, t_bk, t_bv);
    mma_gemm<<<dim3(6, ROWS_T / 128), 256, GSMEM_BYTES>>>(p_ln, p_wqkvT, p_bqkv, nullptr,
                                                          p_qkv, ROWS_T, 768, 256, 0);
    temporal_attn<<<Bq * HWc, 256>>>(tmask);
    mma_gemm<<<dim3(2, ROWS_T / 128), 256, GSMEM_BYTES>>>(p_ao, p_wT2, t_bo, p_x,
                                                          p_x2, ROWS_T, 256, 256, 1);
    cls_avg<<<dim3(4, 8), 256>>>();

    // ---- MLP stage ----
    ln_kernel<<<ROWS_T / 4, 128>>>(p_x2, mln_g, mln_b, p_ln, ROWS_T, 1 << 30, 0);
    mma_gemm<<<dim3(8, ROWS_T / 128), 256, GSMEM_BYTES>>>(p_ln, p_w1T, b1, nullptr,
                                                          p_h, ROWS_T, MLPD, 256, 2);
    mma_gemm<<<dim3(2, ROWS_T / 128), 256, GSMEM_BYTES>>>(p_h, p_w2T, b2, p_x2,
                                                          out, ROWS_T, 256, 1024, 1);
}

// round 5
// speedup vs baseline: 2.4739x; 1.0938x over previous
#include <cuda_runtime.h>
#include <math.h>
#include <stdint.h>

#define Bq 4
#define Tt 8
#define TQn 9
#define HWc 1024
#define Dm 256
#define MLPD 1024
#define ROWS_SP (Bq*Tt*HWc)   /* 32768 */
#define ROWS_T  (Bq*TQn*HWc)  /* 36864 */

// ---------------- scratch (static device globals) ----------------
__device__ float g_ln  [(size_t)ROWS_T * Dm];
__device__ float g_qkv [(size_t)ROWS_T * 768];
__device__ float g_ao  [(size_t)ROWS_T * Dm];
__device__ float g_x   [(size_t)ROWS_T * Dm];
__device__ float g_x2  [(size_t)ROWS_T * Dm];
__device__ float g_h   [(size_t)ROWS_T * MLPD];
__device__ float g_wqkvT[768 * 256];      // [N=768, K=256]
__device__ float g_bqkv[768];
__device__ float g_wT1[256 * 256];        // s_wo^T  [N,K]
__device__ float g_wT2[256 * 256];        // t_wo^T  [N,K]
__device__ float g_w1T[1024 * 256];       // w1^T    [N=1024,K=256]
__device__ float g_w2T[256 * 1024];       // w2^T    [N=256, K=1024]

// ---------------- helpers ----------------
__device__ __forceinline__ float wsum(float v) {
#pragma unroll
    for (int o = 16; o; o >>= 1) v += __shfl_xor_sync(0xffffffffu, v, o);
    return v;
}
__device__ __forceinline__ uint32_t smem_u32(const void* p) {
    uint32_t a;
    asm("{ .reg .u64 t; cvta.to.shared.u64 t, %1; cvt.u32.u64 %0, t; }" : "=r"(a) : "l"(p));
    return a;
}
#define CP_ASYNC16(dst, src) \
    asm volatile("cp.async.cg.shared.global [%0], [%1], 16;" :: "r"(dst), "l"(src))
#define CP_COMMIT() asm volatile("cp.async.commit_group;")
#define CP_WAIT0()  asm volatile("cp.async.wait_group 0;")
#define CP_WAIT1()  asm volatile("cp.async.wait_group 1;")

__device__ __forceinline__ void mma_tf32(float* c, const uint32_t* a, const uint32_t* b) {
    asm volatile(
        "mma.sync.aligned.m16n8k8.row.col.f32.tf32.tf32.f32 "
        "{%0,%1,%2,%3}, {%4,%5,%6,%7}, {%8,%9}, {%0,%1,%2,%3};"
        : "+f"(c[0]), "+f"(c[1]), "+f"(c[2]), "+f"(c[3])
        : "r"(a[0]), "r"(a[1]), "r"(a[2]), "r"(a[3]), "r"(b[0]), "r"(b[1]));
}

// ---------------- weight packing / transpose ----------------
__global__ void pack_qkvT(const float* __restrict__ wq, const float* __restrict__ wk,
                          const float* __restrict__ wv, const float* __restrict__ bq,
                          const float* __restrict__ bk, const float* __restrict__ bv)
{
    int i = blockIdx.x * 256 + threadIdx.x;      // over 768*256
    if (i < 768 * 256) {
        int n = i >> 8, k = i & 255;
        const float* w = (n < 256) ? wq : (n < 512) ? wk : wv;
        int col = n & 255;
        g_wqkvT[i] = w[k * 256 + col];
        if (i < 768)
            g_bqkv[i] = (i < 256) ? bq[i] : (i < 512) ? bk[i - 256] : bv[i - 512];
    }
}

__global__ void transpose_w(const float* __restrict__ in, float* __restrict__ out,
                            int Kd, int Nd)
{
    int i = blockIdx.x * 256 + threadIdx.x;
    if (i < Kd * Nd) {
        int n = i / Kd, k = i % Kd;
        out[i] = in[k * Nd + n];
    }
}

// ---------------- LayerNorm (warp/row, optional row remap) ----------------
__global__ void ln_kernel(const float* __restrict__ X, const float* __restrict__ gam,
                          const float* __restrict__ bet, float* __restrict__ Y,
                          int nrows, int grp, int skip)
{
    int row = blockIdx.x * 4 + (threadIdx.x >> 5);
    if (row >= nrows) return;
    int l = threadIdx.x & 31;
    size_t src = ((size_t)row + (size_t)(row / grp) * skip) * Dm;
    float4 v0 = *(const float4*)(X + src + 4 * l);
    float4 v1 = *(const float4*)(X + src + 128 + 4 * l);
    float s  = v0.x + v0.y + v0.z + v0.w + v1.x + v1.y + v1.z + v1.w;
    float sq = v0.x*v0.x + v0.y*v0.y + v0.z*v0.z + v0.w*v0.w
             + v1.x*v1.x + v1.y*v1.y + v1.z*v1.z + v1.w*v1.w;
    s = wsum(s); sq = wsum(sq);
    float mean = s * (1.f / 256.f);
    float var  = sq * (1.f / 256.f) - mean * mean;
    float rstd = rsqrtf(var + 1e-5f);
    float4 ga0 = *(const float4*)(gam + 4 * l), ga1 = *(const float4*)(gam + 128 + 4 * l);
    float4 be0 = *(const float4*)(bet + 4 * l), be1 = *(const float4*)(bet + 128 + 4 * l);
    float4 o0, o1;
    o0.x = (v0.x - mean) * rstd * ga0.x + be0.x;
    o0.y = (v0.y - mean) * rstd * ga0.y + be0.y;
    o0.z = (v0.z - mean) * rstd * ga0.z + be0.z;
    o0.w = (v0.w - mean) * rstd * ga0.w + be0.w;
    o1.x = (v1.x - mean) * rstd * ga1.x + be1.x;
    o1.y = (v1.y - mean) * rstd * ga1.y + be1.y;
    o1.z = (v1.z - mean) * rstd * ga1.z + be1.z;
    o1.w = (v1.w - mean) * rstd * ga1.w + be1.w;
    *(float4*)(Y + (size_t)row * Dm + 4 * l)       = o0;
    *(float4*)(Y + (size_t)row * Dm + 128 + 4 * l) = o1;
}

// ---------------- tf32 mma.sync GEMM: CTA 128x256, warp 64x64, 3-stage pipeline ----------------
// C[crow,N] = A[M,K] @ B[K,N] + bias ; BT is B^T in [N,K] row-major.
// crow = row + (row/grp)*skip applied to C and res.
// epi bit0: residual add, bit1: exact gelu
#define TSTRIDE 36
#define A_TILEF (128 * TSTRIDE)
#define B_TILEF (256 * TSTRIDE)
#define STAGEF  (A_TILEF + B_TILEF)
#define GSMEM_BYTES (3 * STAGEF * 4)   /* 165,888 B */

__global__ __launch_bounds__(256, 1) void mma_gemm(
    const float* __restrict__ A, const float* __restrict__ BT,
    const float* __restrict__ bias, const float* __restrict__ res,
    float* __restrict__ C, int M, int N, int K, int epi, int grp, int skip)
{
    extern __shared__ float smem[];
    float*   bufA[3]; float* bufB[3];
    uint32_t sA[3], sB[3];
#pragma unroll
    for (int s = 0; s < 3; s++) {
        bufA[s] = smem + s * STAGEF;
        bufB[s] = bufA[s] + A_TILEF;
        sA[s] = smem_u32(bufA[s]);
        sB[s] = smem_u32(bufB[s]);
    }

    int tid = threadIdx.x;
    int wid = tid >> 5, lane = tid & 31;
    int wm = wid >> 2, wn = wid & 3;           // warp grid 2 x 4 -> 64 x 64 each
    int gid = lane >> 2, tig = lane & 3;
    int bx = blockIdx.x, by = blockIdx.y;

    const float* Abase = A  + (size_t)(by * 128) * K;
    const float* Bbase = BT + (size_t)(bx * 256) * K;
    int nch = K >> 5;

    float acc[4][8][4];
#pragma unroll
    for (int i = 0; i < 4; i++)
#pragma unroll
        for (int j = 0; j < 8; j++)
#pragma unroll
            for (int c = 0; c < 4; c++) acc[i][j][c] = 0.f;

    // preload chunks 0,1
#pragma unroll
    for (int p = 0; p < 2; p++) {
        const float* Ag = Abase + p * 32;
        const float* Bg = Bbase + p * 32;
#pragma unroll
        for (int i = 0; i < 4; i++) {          // A: 128 rows x 8 f4
            int idx = i * 256 + tid, row = idx >> 3, c4 = idx & 7;
            CP_ASYNC16(sA[p] + row * (TSTRIDE * 4) + c4 * 16, Ag + (size_t)row * K + c4 * 4);
        }
#pragma unroll
        for (int i = 0; i < 8; i++) {          // B: 256 rows x 8 f4
            int idx = i * 256 + tid, row = idx >> 3, c4 = idx & 7;
            CP_ASYNC16(sB[p] + row * (TSTRIDE * 4) + c4 * 16, Bg + (size_t)row * K + c4 * 4);
        }
        CP_COMMIT();
    }

    int st = 0;
    for (int ch = 0; ch < nch; ch++) {
        if (ch + 1 < nch) CP_WAIT1(); else CP_WAIT0();
        __syncthreads();
        if (ch + 2 < nch) {
            int ps = (st + 2) % 3;
            const float* Ag = Abase + (ch + 2) * 32;
            const float* Bg = Bbase + (ch + 2) * 32;
#pragma unroll
            for (int i = 0; i < 4; i++) {
                int idx = i * 256 + tid, row = idx >> 3, c4 = idx & 7;
                CP_ASYNC16(sA[ps] + row * (TSTRIDE * 4) + c4 * 16, Ag + (size_t)row * K + c4 * 4);
            }
#pragma unroll
            for (int i = 0; i < 8; i++) {
                int idx = i * 256 + tid, row = idx >> 3, c4 = idx & 7;
                CP_ASYNC16(sB[ps] + row * (TSTRIDE * 4) + c4 * 16, Bg + (size_t)row * K + c4 * 4);
            }
            CP_COMMIT();
        }
        const float* Ab = bufA[st];
        const float* Bb = bufB[st];
#pragma unroll
        for (int k0 = 0; k0 < 32; k0 += 8) {
            uint32_t af[4][4], bf[8][2];
#pragma unroll
            for (int mt = 0; mt < 4; mt++) {
                const float* p = Ab + (wm * 64 + mt * 16 + gid) * TSTRIDE + k0 + tig;
                af[mt][0] = __float_as_uint(p[0]);
                af[mt][1] = __float_as_uint(p[8 * TSTRIDE]);
                af[mt][2] = __float_as_uint(p[4]);
                af[mt][3] = __float_as_uint(p[8 * TSTRIDE + 4]);
            }
#pragma unroll
            for (int nt = 0; nt < 8; nt++) {
                const float* p = Bb + (wn * 64 + nt * 8 + gid) * TSTRIDE + k0 + tig;
                bf[nt][0] = __float_as_uint(p[0]);
                bf[nt][1] = __float_as_uint(p[4]);
            }
#pragma unroll
            for (int mt = 0; mt < 4; mt++)
#pragma unroll
                for (int nt = 0; nt < 8; nt++)
                    mma_tf32(acc[mt][nt], af[mt], bf[nt]);
        }
        st = (st + 1) % 3;
    }

    // ---- epilogue ----
#pragma unroll
    for (int mt = 0; mt < 4; mt++) {
#pragma unroll
        for (int half = 0; half < 2; half++) {
            int row = by * 128 + wm * 64 + mt * 16 + gid + half * 8;
            size_t crow = (size_t)row + (size_t)(row / grp) * skip;
#pragma unroll
            for (int nt = 0; nt < 8; nt++) {
                int cc = bx * 256 + wn * 64 + nt * 8 + 2 * tig;
                float2 v;
                v.x = acc[mt][nt][2 * half + 0] + bias[cc];
                v.y = acc[mt][nt][2 * half + 1] + bias[cc + 1];
                size_t base = crow * N + cc;
                if (epi & 1) {
                    float2 rr = *(const float2*)(res + base);
                    v.x += rr.x; v.y += rr.y;
                }
                if (epi & 2) {
                    v.x = 0.5f * v.x * (1.0f + erff(v.x * 0.7071067811865476f));
                    v.y = 0.5f * v.y * (1.0f + erff(v.y * 0.7071067811865476f));
                }
                *(float2*)(C + base) = v;
            }
        }
    }
}

// ---------------- spatial 3x3 windowed attention ----------------
__global__ void spatial_attn()
{
    int r = blockIdx.x;
    int h = threadIdx.x >> 5;
    int l = threadIdx.x & 31;
    int bt = r >> 10, n = r & 1023;
    int y = n >> 5, x = n & 31;
    const float scale = 0.17677669529663687f;

    float q = g_qkv[(size_t)r * 768 + h * 32 + l];
    float sc[9], vv[9];
    bool  ok[9];
#pragma unroll
    for (int kk = 0; kk < 9; kk++) {
        int ny = y + kk / 3 - 1, nx = x + kk % 3 - 1;
        bool v = ((unsigned)ny < 32u) && ((unsigned)nx < 32u);
        ok[kk] = v;
        int rn = v ? ((bt << 10) + (ny << 5) + nx) : r;
        const float* kp = g_qkv + (size_t)rn * 768 + 256 + h * 32;
        float kvv = kp[l];
        vv[kk] = kp[256 + l];
        float d = wsum(q * kvv) * scale;
        sc[kk] = v ? d : -1e30f;
    }
    float m = sc[0];
#pragma unroll
    for (int kk = 1; kk < 9; kk++) m = fmaxf(m, sc[kk]);
    float den = 0.f, o = 0.f;
#pragma unroll
    for (int kk = 0; kk < 9; kk++) {
        float e = ok[kk] ? __expf(sc[kk] - m) : 0.f;
        den += e;
        o += e * vv[kk];
    }
    g_ao[(size_t)r * 256 + h * 32 + l] = o / den;
}

// ---------------- copy frame-8 query rows into g_x ----------------
__global__ void copy_frame8(const float* __restrict__ query)
{
    int blk = blockIdx.x;              // 0..4095 : b*1024 + hw
    int b = blk >> 10, hw = blk & 1023;
    size_t idx = (((size_t)(b * 9 + 8) << 10) + hw) * 256 + threadIdx.x;
    g_x[idx] = query[idx];
}

// ---------------- temporal RoPE attention ----------------
__global__ void temporal_attn(const unsigned char* __restrict__ tmask)
{
    int s = blockIdx.x;
    int h = threadIdx.x >> 5;
    int l = threadIdx.x & 31;
    int b = s >> 10, hw = s & 1023;
    const float scale = 0.17677669529663687f;

    float inv = __powf(10000.f, -(float)(2 * (l & 15)) / 32.f);
    float q[9], k[9], v[9];
#pragma unroll
    for (int t = 0; t < 9; t++) {
        size_t base = ((size_t)(b * 9 + t) * 1024 + hw) * 768 + h * 32;
        float qv = g_qkv[base + l];
        float kv = g_qkv[base + 256 + l];
        v[t]     = g_qkv[base + 512 + l];
        float c, sn;
        sincosf((float)t * inv, &sn, &c);
        float qp = __shfl_xor_sync(0xffffffffu, qv, 16);
        float kp = __shfl_xor_sync(0xffffffffu, kv, 16);
        q[t] = (l < 16) ? (qv * c - qp * sn) : (qp * sn + qv * c);
        k[t] = (l < 16) ? (kv * c - kp * sn) : (kp * sn + kv * c);
    }
#pragma unroll
    for (int tq = 0; tq < 9; tq++) {
        float scr[9];
        float m = -1e30f;
#pragma unroll
        for (int tk = 0; tk < 9; tk++) {
            float d = wsum(q[tq] * k[tk]) * scale;
            if (tmask[tq * 9 + tk]) d = -1e9f;
            scr[tk] = d;
            m = fmaxf(m, d);
        }
        float den = 0.f, o = 0.f;
#pragma unroll
        for (int tk = 0; tk < 9; tk++) {
            float e = __expf(scr[tk] - m);
            den += e;
            o += e * v[tk];
        }
        size_t orow = (size_t)(b * 9 + tq) * 1024 + hw;
        g_ao[orow * 256 + h * 32 + l] = o / den;
    }
}

// ---------------- CLS frame spatial mean + broadcast ----------------
__global__ void cls_avg()
{
    int b = blockIdx.x;
    int d = blockIdx.y * 32 + (threadIdx.x & 31);
    int part = threadIdx.x >> 5;
    float s = 0.f;
    for (int hw = part; hw < 1024; hw += 8)
        s += g_x2[(((size_t)b * 9) * 1024 + hw) * 256 + d];
    __shared__ float sm[8][32];
    sm[part][threadIdx.x & 31] = s;
    __syncthreads();
    if (part == 0) {
        float tot = 0.f;
#pragma unroll
        for (int p = 0; p < 8; p++) tot += sm[p][threadIdx.x & 31];
        sm[0][threadIdx.x & 31] = tot * (1.f / 1024.f);
    }
    __syncthreads();
    float avg = sm[0][threadIdx.x & 31];
    for (int hw = part; hw < 1024; hw += 8)
        g_x2[(((size_t)b * 9) * 1024 + hw) * 256 + d] = avg;
}

// ---------------- launch ----------------
extern "C" void kernel_launch(void* const* d_in, const int* in_sizes, int n_in,
                              void* d_out, int out_size)
{
    const float* query = (const float*)d_in[0];
    const unsigned char* tmask = (const unsigned char*)d_in[2];
    const float* sln_g = (const float*)d_in[3];
    const float* sln_b = (const float*)d_in[4];
    const float* s_wq = (const float*)d_in[5];
    const float* s_bq = (const float*)d_in[6];
    const float* s_wk = (const float*)d_in[7];
    const float* s_bk = (const float*)d_in[8];
    const float* s_wv = (const float*)d_in[9];
    const float* s_bv = (const float*)d_in[10];
    const float* s_wo = (const float*)d_in[11];
    const float* s_bo = (const float*)d_in[12];
    const float* tln_g = (const float*)d_in[13];
    const float* tln_b = (const float*)d_in[14];
    const float* t_wq = (const float*)d_in[15];
    const float* t_bq = (const float*)d_in[16];
    const float* t_wk = (const float*)d_in[17];
    const float* t_bk = (const float*)d_in[18];
    const float* t_wv = (const float*)d_in[19];
    const float* t_bv = (const float*)d_in[20];
    const float* t_wo = (const float*)d_in[21];
    const float* t_bo = (const float*)d_in[22];
    const float* mln_g = (const float*)d_in[23];
    const float* mln_b = (const float*)d_in[24];
    const float* w1 = (const float*)d_in[25];
    const float* b1 = (const float*)d_in[26];
    const float* w2 = (const float*)d_in[27];
    const float* b2 = (const float*)d_in[28];
    float* out = (float*)d_out;

    float *p_ln, *p_qkv, *p_ao, *p_x, *p_x2, *p_h;
    float *p_wqkvT, *p_bqkv, *p_wT1, *p_wT2, *p_w1T, *p_w2T;
    cudaGetSymbolAddress((void**)&p_ln, g_ln);
    cudaGetSymbolAddress((void**)&p_qkv, g_qkv);
    cudaGetSymbolAddress((void**)&p_ao, g_ao);
    cudaGetSymbolAddress((void**)&p_x, g_x);
    cudaGetSymbolAddress((void**)&p_x2, g_x2);
    cudaGetSymbolAddress((void**)&p_h, g_h);
    cudaGetSymbolAddress((void**)&p_wqkvT, g_wqkvT);
    cudaGetSymbolAddress((void**)&p_bqkv, g_bqkv);
    cudaGetSymbolAddress((void**)&p_wT1, g_wT1);
    cudaGetSymbolAddress((void**)&p_wT2, g_wT2);
    cudaGetSymbolAddress((void**)&p_w1T, g_w1T);
    cudaGetSymbolAddress((void**)&p_w2T, g_w2T);

    cudaFuncSetAttribute(mma_gemm, cudaFuncAttributeMaxDynamicSharedMemorySize, GSMEM_BYTES);

    const int NOG = 1 << 30;   // no row remap

    // ---- weight prep ----
    pack_qkvT<<<768, 256>>>(s_wq, s_wk, s_wv, s_bq, s_bk, s_bv);
    transpose_w<<<256, 256>>>(s_wo, p_wT1, 256, 256);
    transpose_w<<<256, 256>>>(t_wo, p_wT2, 256, 256);
    transpose_w<<<1024, 256>>>(w1, p_w1T, 256, 1024);
    transpose_w<<<1024, 256>>>(w2, p_w2T, 1024, 256);

    // ---- spatial stage ----
    ln_kernel<<<ROWS_SP / 4, 128>>>(query, sln_g, sln_b, p_ln, ROWS_SP, 8192, 1024);
    mma_gemm<<<dim3(3, ROWS_SP / 128), 256, GSMEM_BYTES>>>(p_ln, p_wqkvT, p_bqkv, nullptr,
                                                           p_qkv, ROWS_SP, 768, 256, 0, NOG, 0);
    spatial_attn<<<ROWS_SP, 256>>>();
    // O-projection writes straight into g_x rows (b*9+t)*1024+hw with query residual
    mma_gemm<<<dim3(1, ROWS_SP / 128), 256, GSMEM_BYTES>>>(p_ao, p_wT1, s_bo, query,
                                                           p_x, ROWS_SP, 256, 256, 1, 8192, 1024);
    copy_frame8<<<4096, 256>>>(query);

    // ---- temporal stage ----
    ln_kernel<<<ROWS_T / 4, 128>>>(p_x, tln_g, tln_b, p_ln, ROWS_T, NOG, 0);
    pack_qkvT<<<768, 256>>>(t_wq, t_wk, t_wv, t_bq, t_bk, t_bv);
    mma_gemm<<<dim3(3, ROWS_T / 128), 256, GSMEM_BYTES>>>(p_ln, p_wqkvT, p_bqkv, nullptr,
                                                          p_qkv, ROWS_T, 768, 256, 0, NOG, 0);
    temporal_attn<<<Bq * HWc, 256>>>(tmask);
    mma_gemm<<<dim3(1, ROWS_T / 128), 256, GSMEM_BYTES>>>(p_ao, p_wT2, t_bo, p_x,
                                                          p_x2, ROWS_T, 256, 256, 1, NOG, 0);
    cls_avg<<<dim3(4, 8), 256>>>();

    // ---- MLP stage ----
    ln_kernel<<<ROWS_T / 4, 128>>>(p_x2, mln_g, mln_b, p_ln, ROWS_T, NOG, 0);
    mma_gemm<<<dim3(4, ROWS_T / 128), 256, GSMEM_BYTES>>>(p_ln, p_w1T, b1, nullptr,
                                                          p_h, ROWS_T, MLPD, 256, 2, NOG, 0);
    mma_gemm<<<dim3(1, ROWS_T / 128), 256, GSMEM_BYTES>>>(p_h, p_w2T, b2, p_x2,
                                                          out, ROWS_T, 256, 1024, 1, NOG, 0);
}

// round 7
// speedup vs baseline: 3.5350x; 1.4289x over previous
#include <cuda_runtime.h>
#include <cuda_fp16.h>
#include <math.h>
#include <stdint.h>

#define Bq 4
#define Tt 8
#define TQn 9
#define HWc 1024
#define Dm 256
#define MLPD 1024
#define ROWS_SP (Bq*Tt*HWc)   /* 32768 */
#define ROWS_T  (Bq*TQn*HWc)  /* 36864 */

// ---------------- scratch ----------------
__device__ __half g_ln  [(size_t)ROWS_T * Dm];
__device__ float  g_qkv [(size_t)ROWS_T * 768];
__device__ __half g_ao  [(size_t)ROWS_T * Dm];
__device__ float  g_x   [(size_t)ROWS_T * Dm];
__device__ float  g_x2  [(size_t)ROWS_T * Dm];
__device__ __half g_h   [(size_t)ROWS_T * MLPD];
__device__ __half g_wqkvT[768 * 256];     // [N=768,K=256]
__device__ float  g_bqkv[768];
__device__ __half g_wT1[256 * 256];       // s_wo^T [N,K]
__device__ __half g_wT2[256 * 256];       // t_wo^T
__device__ __half g_w1T[1024 * 256];      // w1^T [N,K]
__device__ __half g_w2T[256 * 1024];      // w2^T [N,K]

// ---------------- helpers ----------------
__device__ __forceinline__ float wsum(float v) {
#pragma unroll
    for (int o = 16; o; o >>= 1) v += __shfl_xor_sync(0xffffffffu, v, o);
    return v;
}
__device__ __forceinline__ uint32_t smem_u32(const void* p) {
    uint32_t a;
    asm("{ .reg .u64 t; cvta.to.shared.u64 t, %1; cvt.u32.u64 %0, t; }" : "=r"(a) : "l"(p));
    return a;
}
#define CP_ASYNC16(dst, src) \
    asm volatile("cp.async.cg.shared.global [%0], [%1], 16;" :: "r"(dst), "l"(src))
#define CP_COMMIT() asm volatile("cp.async.commit_group;")
#define CP_WAIT0()  asm volatile("cp.async.wait_group 0;")
#define CP_WAIT1()  asm volatile("cp.async.wait_group 1;")

__device__ __forceinline__ void ldm_x4(uint32_t* r, uint32_t addr) {
    asm volatile("ldmatrix.sync.aligned.m8n8.x4.shared.b16 {%0,%1,%2,%3}, [%4];"
                 : "=r"(r[0]), "=r"(r[1]), "=r"(r[2]), "=r"(r[3]) : "r"(addr));
}
__device__ __forceinline__ void mma_f16(float* c, const uint32_t* a,
                                        uint32_t b0, uint32_t b1) {
    asm volatile(
        "mma.sync.aligned.m16n8k16.row.col.f32.f16.f16.f32 "
        "{%0,%1,%2,%3}, {%4,%5,%6,%7}, {%8,%9}, {%0,%1,%2,%3};"
        : "+f"(c[0]), "+f"(c[1]), "+f"(c[2]), "+f"(c[3])
        : "r"(a[0]), "r"(a[1]), "r"(a[2]), "r"(a[3]), "r"(b0), "r"(b1));
}

// ---------------- weight packing (fp16, transposed [N][K]) ----------------
__global__ void pack_qkvT(const float* __restrict__ wq, const float* __restrict__ wk,
                          const float* __restrict__ wv, const float* __restrict__ bq,
                          const float* __restrict__ bk, const float* __restrict__ bv)
{
    int i = blockIdx.x * 256 + threadIdx.x;      // over 768*256
    if (i < 768 * 256) {
        int n = i >> 8, k = i & 255;
        const float* w = (n < 256) ? wq : (n < 512) ? wk : wv;
        int col = n & 255;
        g_wqkvT[i] = __float2half(w[k * 256 + col]);
        if (i < 768)
            g_bqkv[i] = (i < 256) ? bq[i] : (i < 512) ? bk[i - 256] : bv[i - 512];
    }
}

__global__ void transpose_w(const float* __restrict__ in, __half* __restrict__ out,
                            int Kd, int Nd)
{
    int i = blockIdx.x * 256 + threadIdx.x;
    if (i < Kd * Nd) {
        int n = i / Kd, k = i % Kd;
        out[i] = __float2half(in[k * Nd + n]);
    }
}

// ---------------- LayerNorm: fp32 in -> fp16 out ----------------
__global__ void ln_kernel(const float* __restrict__ X, const float* __restrict__ gam,
                          const float* __restrict__ bet, __half* __restrict__ Y,
                          int nrows, int grp, int skip)
{
    int row = blockIdx.x * 4 + (threadIdx.x >> 5);
    if (row >= nrows) return;
    int l = threadIdx.x & 31;
    size_t src = ((size_t)row + (size_t)(row / grp) * skip) * Dm;
    float4 v0 = *(const float4*)(X + src + 4 * l);
    float4 v1 = *(const float4*)(X + src + 128 + 4 * l);
    float s  = v0.x + v0.y + v0.z + v0.w + v1.x + v1.y + v1.z + v1.w;
    float sq = v0.x*v0.x + v0.y*v0.y + v0.z*v0.z + v0.w*v0.w
             + v1.x*v1.x + v1.y*v1.y + v1.z*v1.z + v1.w*v1.w;
    s = wsum(s); sq = wsum(sq);
    float mean = s * (1.f / 256.f);
    float var  = sq * (1.f / 256.f) - mean * mean;
    float rstd = rsqrtf(var + 1e-5f);
    float4 ga0 = *(const float4*)(gam + 4 * l), ga1 = *(const float4*)(gam + 128 + 4 * l);
    float4 be0 = *(const float4*)(bet + 4 * l), be1 = *(const float4*)(bet + 128 + 4 * l);
    __half2 h0 = __floats2half2_rn((v0.x - mean) * rstd * ga0.x + be0.x,
                                   (v0.y - mean) * rstd * ga0.y + be0.y);
    __half2 h1 = __floats2half2_rn((v0.z - mean) * rstd * ga0.z + be0.z,
                                   (v0.w - mean) * rstd * ga0.w + be0.w);
    __half2 h2 = __floats2half2_rn((v1.x - mean) * rstd * ga1.x + be1.x,
                                   (v1.y - mean) * rstd * ga1.y + be1.y);
    __half2 h3 = __floats2half2_rn((v1.z - mean) * rstd * ga1.z + be1.z,
                                   (v1.w - mean) * rstd * ga1.w + be1.w);
    uint2 u0 = { *(uint32_t*)&h0, *(uint32_t*)&h1 };
    uint2 u1 = { *(uint32_t*)&h2, *(uint32_t*)&h3 };
    *(uint2*)(Y + (size_t)row * Dm + 4 * l)       = u0;
    *(uint2*)(Y + (size_t)row * Dm + 128 + 4 * l) = u1;
}

// ---------------- fp16 mma.sync GEMM: CTA 128x256, warp 64x64, 3-stage, ldmatrix ----------------
// C = A(fp16)[M,K] @ B(fp16,[N][K]) + bias(fp32); crow = row + (row/grp)*skip on C/res.
// epi bit0: residual add (fp32 res), bit1: exact gelu, bit2: fp16 output to Ch (else fp32 to C)
#define ARS 80                         /* A/B smem row stride, bytes */
#define A_BYTES (128 * ARS)            /* 10240 */
#define B_BYTES (256 * ARS)            /* 20480 */
#define STAGE_B (A_BYTES + B_BYTES)    /* 30720 */
#define GSMEM_BYTES (3 * STAGE_B)      /* 92160 */

__global__ __launch_bounds__(256, 1) void mma_gemm(
    const __half* __restrict__ A, const __half* __restrict__ BT,
    const float* __restrict__ bias, const float* __restrict__ res,
    float* __restrict__ C, __half* __restrict__ Ch,
    int M, int N, int K, int epi, int grp, int skip)
{
    extern __shared__ char smem[];
    uint32_t sbase = smem_u32(smem);

    int tid = threadIdx.x;
    int wid = tid >> 5, lane = tid & 31;
    int wm = wid >> 2, wn = wid & 3;           // 2 x 4 warps -> 64x64 tiles
    int gid = lane >> 2, tig = lane & 3;
    int i8 = lane & 7, bit0 = (lane >> 3) & 1, bit1 = lane >> 4;
    int bx = blockIdx.x, by = blockIdx.y;

    const __half* Abase = A  + (size_t)(by * 128) * K;
    const __half* Bbase = BT + (size_t)(bx * 256) * K;
    int nch = K >> 5;

    float acc[4][8][4];
#pragma unroll
    for (int i = 0; i < 4; i++)
#pragma unroll
        for (int j = 0; j < 8; j++)
#pragma unroll
            for (int c = 0; c < 4; c++) acc[i][j][c] = 0.f;

    // per-thread cp.async indices
    // A: 2 chunks: id = tid + i*256 -> row = id>>2, q = id&3
    // B: 4 chunks: id = tid + i*256 -> row = id>>2, q = id&3
#pragma unroll
    for (int p = 0; p < 2; p++) {
        uint32_t stA = sbase + p * STAGE_B;
        uint32_t stB = stA + A_BYTES;
        const __half* Ag = Abase + p * 32;
        const __half* Bg = Bbase + p * 32;
#pragma unroll
        for (int i = 0; i < 2; i++) {
            int id = tid + i * 256, row = id >> 2, q = id & 3;
            CP_ASYNC16(stA + row * ARS + q * 16, Ag + (size_t)row * K + q * 8);
        }
#pragma unroll
        for (int i = 0; i < 4; i++) {
            int id = tid + i * 256, row = id >> 2, q = id & 3;
            CP_ASYNC16(stB + row * ARS + q * 16, Bg + (size_t)row * K + q * 8);
        }
        CP_COMMIT();
    }

    // ldmatrix base offsets (within stage)
    uint32_t aOff = (uint32_t)((wm * 64 + bit0 * 8 + i8) * ARS + bit1 * 16);
    uint32_t bOff = (uint32_t)(A_BYTES + (wn * 64 + bit1 * 8 + i8) * ARS + bit0 * 16);

    int st = 0;
    for (int ch = 0; ch < nch; ch++) {
        if (ch + 1 < nch) CP_WAIT1(); else CP_WAIT0();
        __syncthreads();
        if (ch + 2 < nch) {
            int ps = st + 2; if (ps >= 3) ps -= 3;
            uint32_t stA = sbase + ps * STAGE_B;
            uint32_t stB = stA + A_BYTES;
            const __half* Ag = Abase + (ch + 2) * 32;
            const __half* Bg = Bbase + (ch + 2) * 32;
#pragma unroll
            for (int i = 0; i < 2; i++) {
                int id = tid + i * 256, row = id >> 2, q = id & 3;
                CP_ASYNC16(stA + row * ARS + q * 16, Ag + (size_t)row * K + q * 8);
            }
#pragma unroll
            for (int i = 0; i < 4; i++) {
                int id = tid + i * 256, row = id >> 2, q = id & 3;
                CP_ASYNC16(stB + row * ARS + q * 16, Bg + (size_t)row * K + q * 8);
            }
            CP_COMMIT();
        }
        uint32_t stg = sbase + st * STAGE_B;
#pragma unroll
        for (int k16 = 0; k16 < 2; k16++) {
            uint32_t af[4][4], bf[4][4];
            uint32_t aA = stg + aOff + k16 * 32;
            uint32_t bA = stg + bOff + k16 * 32;
#pragma unroll
            for (int mt = 0; mt < 4; mt++) ldm_x4(af[mt], aA + mt * (16 * ARS));
#pragma unroll
            for (int p = 0; p < 4; p++)   ldm_x4(bf[p], bA + p * (16 * ARS));
#pragma unroll
            for (int mt = 0; mt < 4; mt++)
#pragma unroll
                for (int p = 0; p < 4; p++) {
                    mma_f16(acc[mt][2 * p],     af[mt], bf[p][0], bf[p][1]);
                    mma_f16(acc[mt][2 * p + 1], af[mt], bf[p][2], bf[p][3]);
                }
        }
        st++; if (st == 3) st = 0;
    }

    // ---- epilogue ----
#pragma unroll
    for (int mt = 0; mt < 4; mt++) {
#pragma unroll
        for (int half = 0; half < 2; half++) {
            int row = by * 128 + wm * 64 + mt * 16 + gid + half * 8;
            size_t crow = (size_t)row + (size_t)(row / grp) * skip;
#pragma unroll
            for (int n8 = 0; n8 < 8; n8++) {
                int cc = bx * 256 + wn * 64 + n8 * 8 + 2 * tig;
                float2 v;
                v.x = acc[mt][n8][2 * half + 0] + bias[cc];
                v.y = acc[mt][n8][2 * half + 1] + bias[cc + 1];
                size_t base = crow * (size_t)N + cc;
                if (epi & 1) {
                    float2 rr = *(const float2*)(res + base);
                    v.x += rr.x; v.y += rr.y;
                }
                if (epi & 2) {
                    v.x = 0.5f * v.x * (1.0f + erff(v.x * 0.7071067811865476f));
                    v.y = 0.5f * v.y * (1.0f + erff(v.y * 0.7071067811865476f));
                }
                if (epi & 4) {
                    __half2 h = __floats2half2_rn(v.x, v.y);
                    *(__half2*)(Ch + base) = h;
                } else {
                    *(float2*)(C + base) = v;
                }
            }
        }
    }
}

// ---------------- spatial 3x3 windowed attention (fp16 out) ----------------
__global__ void spatial_attn()
{
    int r = blockIdx.x;
    int h = threadIdx.x >> 5;
    int l = threadIdx.x & 31;
    int bt = r >> 10, n = r & 1023;
    int y = n >> 5, x = n & 31;
    const float scale = 0.17677669529663687f;

    float q = g_qkv[(size_t)r * 768 + h * 32 + l];
    float sc[9], vv[9];
    bool  ok[9];
#pragma unroll
    for (int kk = 0; kk < 9; kk++) {
        int ny = y + kk / 3 - 1, nx = x + kk % 3 - 1;
        bool v = ((unsigned)ny < 32u) && ((unsigned)nx < 32u);
        ok[kk] = v;
        int rn = v ? ((bt << 10) + (ny << 5) + nx) : r;
        const float* kp = g_qkv + (size_t)rn * 768 + 256 + h * 32;
        float kvv = kp[l];
        vv[kk] = kp[256 + l];
        float d = wsum(q * kvv) * scale;
        sc[kk] = v ? d : -1e30f;
    }
    float m = sc[0];
#pragma unroll
    for (int kk = 1; kk < 9; kk++) m = fmaxf(m, sc[kk]);
    float den = 0.f, o = 0.f;
#pragma unroll
    for (int kk = 0; kk < 9; kk++) {
        float e = ok[kk] ? __expf(sc[kk] - m) : 0.f;
        den += e;
        o += e * vv[kk];
    }
    g_ao[(size_t)r * 256 + h * 32 + l] = __float2half(o / den);
}

// ---------------- copy frame-8 query rows into g_x ----------------
__global__ void copy_frame8(const float* __restrict__ query)
{
    int blk = blockIdx.x;
    int b = blk >> 10, hw = blk & 1023;
    size_t idx = (((size_t)(b * 9 + 8) << 10) + hw) * 256 + threadIdx.x;
    g_x[idx] = query[idx];
}

// ---------------- temporal RoPE attention (fp16 out) ----------------
__global__ void temporal_attn(const unsigned char* __restrict__ tmask)
{
    int s = blockIdx.x;
    int h = threadIdx.x >> 5;
    int l = threadIdx.x & 31;
    int b = s >> 10, hw = s & 1023;
    const float scale = 0.17677669529663687f;

    float inv = __powf(10000.f, -(float)(2 * (l & 15)) / 32.f);
    float q[9], k[9], v[9];
#pragma unroll
    for (int t = 0; t < 9; t++) {
        size_t base = ((size_t)(b * 9 + t) * 1024 + hw) * 768 + h * 32;
        float qv = g_qkv[base + l];
        float kv = g_qkv[base + 256 + l];
        v[t]     = g_qkv[base + 512 + l];
        float c, sn;
        sincosf((float)t * inv, &sn, &c);
        float qp = __shfl_xor_sync(0xffffffffu, qv, 16);
        float kp = __shfl_xor_sync(0xffffffffu, kv, 16);
        q[t] = (l < 16) ? (qv * c - qp * sn) : (qp * sn + qv * c);
        k[t] = (l < 16) ? (kv * c - kp * sn) : (kp * sn + kv * c);
    }
#pragma unroll
    for (int tq = 0; tq < 9; tq++) {
        float scr[9];
        float m = -1e30f;
#pragma unroll
        for (int tk = 0; tk < 9; tk++) {
            float d = wsum(q[tq] * k[tk]) * scale;
            if (tmask[tq * 9 + tk]) d = -1e9f;
            scr[tk] = d;
            m = fmaxf(m, d);
        }
        float den = 0.f, o = 0.f;
#pragma unroll
        for (int tk = 0; tk < 9; tk++) {
            float e = __expf(scr[tk] - m);
            den += e;
            o += e * v[tk];
        }
        size_t orow = (size_t)(b * 9 + tq) * 1024 + hw;
        g_ao[orow * 256 + h * 32 + l] = __float2half(o / den);
    }
}

// ---------------- CLS frame spatial mean + broadcast ----------------
__global__ void cls_avg()
{
    int b = blockIdx.x;
    int d = blockIdx.y * 32 + (threadIdx.x & 31);
    int part = threadIdx.x >> 5;
    float s = 0.f;
    for (int hw = part; hw < 1024; hw += 8)
        s += g_x2[(((size_t)b * 9) * 1024 + hw) * 256 + d];
    __shared__ float sm[8][32];
    sm[part][threadIdx.x & 31] = s;
    __syncthreads();
    if (part == 0) {
        float tot = 0.f;
#pragma unroll
        for (int p = 0; p < 8; p++) tot += sm[p][threadIdx.x & 31];
        sm[0][threadIdx.x & 31] = tot * (1.f / 1024.f);
    }
    __syncthreads();
    float avg = sm[0][threadIdx.x & 31];
    for (int hw = part; hw < 1024; hw += 8)
        g_x2[(((size_t)b * 9) * 1024 + hw) * 256 + d] = avg;
}

// ---------------- launch ----------------
extern "C" void kernel_launch(void* const* d_in, const int* in_sizes, int n_in,
                              void* d_out, int out_size)
{
    const float* query = (const float*)d_in[0];
    const unsigned char* tmask = (const unsigned char*)d_in[2];
    const float* sln_g = (const float*)d_in[3];
    const float* sln_b = (const float*)d_in[4];
    const float* s_wq = (const float*)d_in[5];
    const float* s_bq = (const float*)d_in[6];
    const float* s_wk = (const float*)d_in[7];
    const float* s_bk = (const float*)d_in[8];
    const float* s_wv = (const float*)d_in[9];
    const float* s_bv = (const float*)d_in[10];
    const float* s_wo = (const float*)d_in[11];
    const float* s_bo = (const float*)d_in[12];
    const float* tln_g = (const float*)d_in[13];
    const float* tln_b = (const float*)d_in[14];
    const float* t_wq = (const float*)d_in[15];
    const float* t_bq = (const float*)d_in[16];
    const float* t_wk = (const float*)d_in[17];
    const float* t_bk = (const float*)d_in[18];
    const float* t_wv = (const float*)d_in[19];
    const float* t_bv = (const float*)d_in[20];
    const float* t_wo = (const float*)d_in[21];
    const float* t_bo = (const float*)d_in[22];
    const float* mln_g = (const float*)d_in[23];
    const float* mln_b = (const float*)d_in[24];
    const float* w1 = (const float*)d_in[25];
    const float* b1 = (const float*)d_in[26];
    const float* w2 = (const float*)d_in[27];
    const float* b2 = (const float*)d_in[28];
    float* out = (float*)d_out;

    __half *p_ln, *p_ao, *p_h, *p_wqkvT, *p_wT1, *p_wT2, *p_w1T, *p_w2T;
    float *p_qkv, *p_x, *p_x2, *p_bqkv;
    cudaGetSymbolAddress((void**)&p_ln, g_ln);
    cudaGetSymbolAddress((void**)&p_qkv, g_qkv);
    cudaGetSymbolAddress((void**)&p_ao, g_ao);
    cudaGetSymbolAddress((void**)&p_x, g_x);
    cudaGetSymbolAddress((void**)&p_x2, g_x2);
    cudaGetSymbolAddress((void**)&p_h, g_h);
    cudaGetSymbolAddress((void**)&p_wqkvT, g_wqkvT);
    cudaGetSymbolAddress((void**)&p_bqkv, g_bqkv);
    cudaGetSymbolAddress((void**)&p_wT1, g_wT1);
    cudaGetSymbolAddress((void**)&p_wT2, g_wT2);
    cudaGetSymbolAddress((void**)&p_w1T, g_w1T);
    cudaGetSymbolAddress((void**)&p_w2T, g_w2T);

    cudaFuncSetAttribute(mma_gemm, cudaFuncAttributeMaxDynamicSharedMemorySize, GSMEM_BYTES);

    const int NOG = 1 << 30;

    // ---- weight prep ----
    pack_qkvT<<<768, 256>>>(s_wq, s_wk, s_wv, s_bq, s_bk, s_bv);
    transpose_w<<<256, 256>>>(s_wo, p_wT1, 256, 256);
    transpose_w<<<256, 256>>>(t_wo, p_wT2, 256, 256);
    transpose_w<<<1024, 256>>>(w1, p_w1T, 256, 1024);
    transpose_w<<<1024, 256>>>(w2, p_w2T, 1024, 256);

    // ---- spatial stage ----
    ln_kernel<<<ROWS_SP / 4, 128>>>(query, sln_g, sln_b, p_ln, ROWS_SP, 8192, 1024);
    mma_gemm<<<dim3(3, ROWS_SP / 128), 256, GSMEM_BYTES>>>(p_ln, p_wqkvT, p_bqkv, nullptr,
            p_qkv, nullptr, ROWS_SP, 768, 256, 0, NOG, 0);
    spatial_attn<<<ROWS_SP, 256>>>();
    mma_gemm<<<dim3(1, ROWS_SP / 128), 256, GSMEM_BYTES>>>(p_ao, p_wT1, s_bo, query,
            p_x, nullptr, ROWS_SP, 256, 256, 1, 8192, 1024);
    copy_frame8<<<4096, 256>>>(query);

    // ---- temporal stage ----
    ln_kernel<<<ROWS_T / 4, 128>>>(p_x, tln_g, tln_b, p_ln, ROWS_T, NOG, 0);
    pack_qkvT<<<768, 256>>>(t_wq, t_wk, t_wv, t_bq, t_bk, t_bv);
    mma_gemm<<<dim3(3, ROWS_T / 128), 256, GSMEM_BYTES>>>(p_ln, p_wqkvT, p_bqkv, nullptr,
            p_qkv, nullptr, ROWS_T, 768, 256, 0, NOG, 0);
    temporal_attn<<<Bq * HWc, 256>>>(tmask);
    mma_gemm<<<dim3(1, ROWS_T / 128), 256, GSMEM_BYTES>>>(p_ao, p_wT2, t_bo, p_x,
            p_x2, nullptr, ROWS_T, 256, 256, 1, NOG, 0);
    cls_avg<<<dim3(4, 8), 256>>>();

    // ---- MLP stage ----
    ln_kernel<<<ROWS_T / 4, 128>>>(p_x2, mln_g, mln_b, p_ln, ROWS_T, NOG, 0);
    mma_gemm<<<dim3(4, ROWS_T / 128), 256, GSMEM_BYTES>>>(p_ln, p_w1T, b1, nullptr,
            nullptr, p_h, ROWS_T, MLPD, 256, 2 | 4, NOG, 0);
    mma_gemm<<<dim3(1, ROWS_T / 128), 256, GSMEM_BYTES>>>(p_h, p_w2T, b2, p_x2,
            out, nullptr, ROWS_T, 256, 1024, 1, NOG, 0);
}

// round 8
// speedup vs baseline: 3.9952x; 1.1302x over previous
#include <cuda_runtime.h>
#include <cuda_fp16.h>
#include <math.h>
#include <stdint.h>

#define Bq 4
#define Tt 8
#define TQn 9
#define HWc 1024
#define Dm 256
#define MLPD 1024
#define ROWS_SP (Bq*Tt*HWc)   /* 32768 */
#define ROWS_T  (Bq*TQn*HWc)  /* 36864 */

// ---------------- scratch ----------------
__device__ __half g_ln  [(size_t)ROWS_T * Dm];
__device__ __half g_qkv [(size_t)ROWS_T * 768];
__device__ __half g_ao  [(size_t)ROWS_T * Dm];
__device__ float  g_x   [(size_t)ROWS_T * Dm];
__device__ float  g_x2  [(size_t)ROWS_T * Dm];
__device__ __half g_h   [(size_t)ROWS_T * MLPD];
__device__ __half g_wqkvT[768 * 256];     // [N=768,K=256]
__device__ float  g_bqkv[768];
__device__ __half g_wT1[256 * 256];       // s_wo^T [N,K]
__device__ __half g_wT2[256 * 256];       // t_wo^T
__device__ __half g_w1T[1024 * 256];      // w1^T [N,K]
__device__ __half g_w2T[256 * 1024];      // w2^T [N,K]

// ---------------- helpers ----------------
__device__ __forceinline__ float wsum(float v) {
#pragma unroll
    for (int o = 16; o; o >>= 1) v += __shfl_xor_sync(0xffffffffu, v, o);
    return v;
}
__device__ __forceinline__ float hsum16(float v) {   // butterfly over 16-lane group
#pragma unroll
    for (int o = 8; o; o >>= 1) v += __shfl_xor_sync(0xffffffffu, v, o);
    return v;
}
__device__ __forceinline__ uint32_t smem_u32(const void* p) {
    uint32_t a;
    asm("{ .reg .u64 t; cvta.to.shared.u64 t, %1; cvt.u32.u64 %0, t; }" : "=r"(a) : "l"(p));
    return a;
}
#define CP_ASYNC16(dst, src) \
    asm volatile("cp.async.cg.shared.global [%0], [%1], 16;" :: "r"(dst), "l"(src))
#define CP_COMMIT() asm volatile("cp.async.commit_group;")
#define CP_WAIT0()  asm volatile("cp.async.wait_group 0;")
#define CP_WAIT1()  asm volatile("cp.async.wait_group 1;")

__device__ __forceinline__ void ldm_x4(uint32_t* r, uint32_t addr) {
    asm volatile("ldmatrix.sync.aligned.m8n8.x4.shared.b16 {%0,%1,%2,%3}, [%4];"
                 : "=r"(r[0]), "=r"(r[1]), "=r"(r[2]), "=r"(r[3]) : "r"(addr));
}
__device__ __forceinline__ void mma_f16(float* c, const uint32_t* a,
                                        uint32_t b0, uint32_t b1) {
    asm volatile(
        "mma.sync.aligned.m16n8k16.row.col.f32.f16.f16.f32 "
        "{%0,%1,%2,%3}, {%4,%5,%6,%7}, {%8,%9}, {%0,%1,%2,%3};"
        : "+f"(c[0]), "+f"(c[1]), "+f"(c[2]), "+f"(c[3])
        : "r"(a[0]), "r"(a[1]), "r"(a[2]), "r"(a[3]), "r"(b0), "r"(b1));
}

// ---------------- weight packing ----------------
__global__ void pack_qkvT(const float* __restrict__ wq, const float* __restrict__ wk,
                          const float* __restrict__ wv, const float* __restrict__ bq,
                          const float* __restrict__ bk, const float* __restrict__ bv)
{
    int i = blockIdx.x * 256 + threadIdx.x;
    if (i < 768 * 256) {
        int n = i >> 8, k = i & 255;
        const float* w = (n < 256) ? wq : (n < 512) ? wk : wv;
        int col = n & 255;
        g_wqkvT[i] = __float2half(w[k * 256 + col]);
        if (i < 768)
            g_bqkv[i] = (i < 256) ? bq[i] : (i < 512) ? bk[i - 256] : bv[i - 512];
    }
}

__global__ void transpose_w(const float* __restrict__ in, __half* __restrict__ out,
                            int Kd, int Nd)
{
    int i = blockIdx.x * 256 + threadIdx.x;
    if (i < Kd * Nd) {
        int n = i / Kd, k = i % Kd;
        out[i] = __float2half(in[k * Nd + n]);
    }
}

// ---------------- LayerNorm: fp32 in -> fp16 out ----------------
__global__ void ln_kernel(const float* __restrict__ X, const float* __restrict__ gam,
                          const float* __restrict__ bet, __half* __restrict__ Y,
                          int nrows, int grp, int skip)
{
    int row = blockIdx.x * 4 + (threadIdx.x >> 5);
    if (row >= nrows) return;
    int l = threadIdx.x & 31;
    size_t src = ((size_t)row + (size_t)(row / grp) * skip) * Dm;
    float4 v0 = *(const float4*)(X + src + 4 * l);
    float4 v1 = *(const float4*)(X + src + 128 + 4 * l);
    float s  = v0.x + v0.y + v0.z + v0.w + v1.x + v1.y + v1.z + v1.w;
    float sq = v0.x*v0.x + v0.y*v0.y + v0.z*v0.z + v0.w*v0.w
             + v1.x*v1.x + v1.y*v1.y + v1.z*v1.z + v1.w*v1.w;
    s = wsum(s); sq = wsum(sq);
    float mean = s * (1.f / 256.f);
    float var  = sq * (1.f / 256.f) - mean * mean;
    float rstd = rsqrtf(var + 1e-5f);
    float4 ga0 = *(const float4*)(gam + 4 * l), ga1 = *(const float4*)(gam + 128 + 4 * l);
    float4 be0 = *(const float4*)(bet + 4 * l), be1 = *(const float4*)(bet + 128 + 4 * l);
    __half2 h0 = __floats2half2_rn((v0.x - mean) * rstd * ga0.x + be0.x,
                                   (v0.y - mean) * rstd * ga0.y + be0.y);
    __half2 h1 = __floats2half2_rn((v0.z - mean) * rstd * ga0.z + be0.z,
                                   (v0.w - mean) * rstd * ga0.w + be0.w);
    __half2 h2 = __floats2half2_rn((v1.x - mean) * rstd * ga1.x + be1.x,
                                   (v1.y - mean) * rstd * ga1.y + be1.y);
    __half2 h3 = __floats2half2_rn((v1.z - mean) * rstd * ga1.z + be1.z,
                                   (v1.w - mean) * rstd * ga1.w + be1.w);
    uint2 u0 = { *(uint32_t*)&h0, *(uint32_t*)&h1 };
    uint2 u1 = { *(uint32_t*)&h2, *(uint32_t*)&h3 };
    *(uint2*)(Y + (size_t)row * Dm + 4 * l)       = u0;
    *(uint2*)(Y + (size_t)row * Dm + 128 + 4 * l) = u1;
}

// ---------------- fp16 mma.sync GEMM: CTA 128x256, warp 64x64, 3-stage, ldmatrix ----------------
// epi bit0: residual add (fp32), bit1: exact gelu, bit2: fp16 output to Ch (else fp32 to C)
#define ARS 80
#define A_BYTES (128 * ARS)
#define B_BYTES (256 * ARS)
#define STAGE_B (A_BYTES + B_BYTES)
#define GSMEM_BYTES (3 * STAGE_B)      /* 92160 */

__global__ __launch_bounds__(256, 1) void mma_gemm(
    const __half* __restrict__ A, const __half* __restrict__ BT,
    const float* __restrict__ bias, const float* __restrict__ res,
    float* __restrict__ C, __half* __restrict__ Ch,
    int M, int N, int K, int epi, int grp, int skip)
{
    extern __shared__ char smem[];
    uint32_t sbase = smem_u32(smem);

    int tid = threadIdx.x;
    int wid = tid >> 5, lane = tid & 31;
    int wm = wid >> 2, wn = wid & 3;
    int gid = lane >> 2, tig = lane & 3;
    int i8 = lane & 7, bit0 = (lane >> 3) & 1, bit1 = lane >> 4;
    int bx = blockIdx.x, by = blockIdx.y;

    const __half* Abase = A  + (size_t)(by * 128) * K;
    const __half* Bbase = BT + (size_t)(bx * 256) * K;
    int nch = K >> 5;

    float acc[4][8][4];
#pragma unroll
    for (int i = 0; i < 4; i++)
#pragma unroll
        for (int j = 0; j < 8; j++)
#pragma unroll
            for (int c = 0; c < 4; c++) acc[i][j][c] = 0.f;

#pragma unroll
    for (int p = 0; p < 2; p++) {
        uint32_t stA = sbase + p * STAGE_B;
        uint32_t stB = stA + A_BYTES;
        const __half* Ag = Abase + p * 32;
        const __half* Bg = Bbase + p * 32;
#pragma unroll
        for (int i = 0; i < 2; i++) {
            int id = tid + i * 256, row = id >> 2, q = id & 3;
            CP_ASYNC16(stA + row * ARS + q * 16, Ag + (size_t)row * K + q * 8);
        }
#pragma unroll
        for (int i = 0; i < 4; i++) {
            int id = tid + i * 256, row = id >> 2, q = id & 3;
            CP_ASYNC16(stB + row * ARS + q * 16, Bg + (size_t)row * K + q * 8);
        }
        CP_COMMIT();
    }

    uint32_t aOff = (uint32_t)((wm * 64 + bit0 * 8 + i8) * ARS + bit1 * 16);
    uint32_t bOff = (uint32_t)(A_BYTES + (wn * 64 + bit1 * 8 + i8) * ARS + bit0 * 16);

    int st = 0;
    for (int ch = 0; ch < nch; ch++) {
        if (ch + 1 < nch) CP_WAIT1(); else CP_WAIT0();
        __syncthreads();
        if (ch + 2 < nch) {
            int ps = st + 2; if (ps >= 3) ps -= 3;
            uint32_t stA = sbase + ps * STAGE_B;
            uint32_t stB = stA + A_BYTES;
            const __half* Ag = Abase + (ch + 2) * 32;
            const __half* Bg = Bbase + (ch + 2) * 32;
#pragma unroll
            for (int i = 0; i < 2; i++) {
                int id = tid + i * 256, row = id >> 2, q = id & 3;
                CP_ASYNC16(stA + row * ARS + q * 16, Ag + (size_t)row * K + q * 8);
            }
#pragma unroll
            for (int i = 0; i < 4; i++) {
                int id = tid + i * 256, row = id >> 2, q = id & 3;
                CP_ASYNC16(stB + row * ARS + q * 16, Bg + (size_t)row * K + q * 8);
            }
            CP_COMMIT();
        }
        uint32_t stg = sbase + st * STAGE_B;
#pragma unroll
        for (int k16 = 0; k16 < 2; k16++) {
            uint32_t af[4][4], bf[4][4];
            uint32_t aA = stg + aOff + k16 * 32;
            uint32_t bA = stg + bOff + k16 * 32;
#pragma unroll
            for (int mt = 0; mt < 4; mt++) ldm_x4(af[mt], aA + mt * (16 * ARS));
#pragma unroll
            for (int p = 0; p < 4; p++)   ldm_x4(bf[p], bA + p * (16 * ARS));
#pragma unroll
            for (int mt = 0; mt < 4; mt++)
#pragma unroll
                for (int p = 0; p < 4; p++) {
                    mma_f16(acc[mt][2 * p],     af[mt], bf[p][0], bf[p][1]);
                    mma_f16(acc[mt][2 * p + 1], af[mt], bf[p][2], bf[p][3]);
                }
        }
        st++; if (st == 3) st = 0;
    }

    // ---- epilogue ----
#pragma unroll
    for (int mt = 0; mt < 4; mt++) {
#pragma unroll
        for (int half = 0; half < 2; half++) {
            int row = by * 128 + wm * 64 + mt * 16 + gid + half * 8;
            size_t crow = (size_t)row + (size_t)(row / grp) * skip;
#pragma unroll
            for (int n8 = 0; n8 < 8; n8++) {
                int cc = bx * 256 + wn * 64 + n8 * 8 + 2 * tig;
                float2 v;
                v.x = acc[mt][n8][2 * half + 0] + bias[cc];
                v.y = acc[mt][n8][2 * half + 1] + bias[cc + 1];
                size_t base = crow * (size_t)N + cc;
                if (epi & 1) {
                    float2 rr = *(const float2*)(res + base);
                    v.x += rr.x; v.y += rr.y;
                }
                if (epi & 2) {
                    v.x = 0.5f * v.x * (1.0f + erff(v.x * 0.7071067811865476f));
                    v.y = 0.5f * v.y * (1.0f + erff(v.y * 0.7071067811865476f));
                }
                if (epi & 4) {
                    __half2 h = __floats2half2_rn(v.x, v.y);
                    *(__half2*)(Ch + base) = h;
                } else {
                    *(float2*)(C + base) = v;
                }
            }
        }
    }
}

// ---------------- spatial 3x3 windowed attention: 128 thr/token, 2 heads/warp, half2 lanes ----
__global__ void spatial_attn()
{
    int r = blockIdx.x;                 // token
    int w = threadIdx.x >> 5;           // warp 0..3
    int l = threadIdx.x & 31;
    int head = 2 * w + (l >> 4);
    int hl = l & 15;                    // half2 index within head (dims 2hl, 2hl+1)
    int bt = r >> 10, n = r & 1023;
    int y = n >> 5, x = n & 31;
    const float scale = 0.17677669529663687f;

    const __half2* qp = (const __half2*)(g_qkv + (size_t)r * 768 + head * 32) + hl;
    float2 q = __half22float2(*qp);

    float sc[9];
    uint32_t vv[9];
    bool ok[9];
#pragma unroll
    for (int kk = 0; kk < 9; kk++) {
        int ny = y + kk / 3 - 1, nx = x + kk % 3 - 1;
        bool valid = ((unsigned)ny < 32u) && ((unsigned)nx < 32u);
        ok[kk] = valid;
        int rn = valid ? ((bt << 10) + (ny << 5) + nx) : r;
        const __half2* kp = (const __half2*)(g_qkv + (size_t)rn * 768 + 256 + head * 32) + hl;
        float2 kv = __half22float2(*kp);
        vv[kk] = *(const uint32_t*)((const __half2*)(g_qkv + (size_t)rn * 768 + 512 + head * 32) + hl);
        float d = hsum16(q.x * kv.x + q.y * kv.y) * scale;
        sc[kk] = valid ? d : -1e30f;
    }
    float m = sc[0];
#pragma unroll
    for (int kk = 1; kk < 9; kk++) m = fmaxf(m, sc[kk]);
    float den = 0.f;
    float2 o = make_float2(0.f, 0.f);
#pragma unroll
    for (int kk = 0; kk < 9; kk++) {
        float e = ok[kk] ? __expf(sc[kk] - m) : 0.f;
        den += e;
        float2 vf = __half22float2(*(const __half2*)&vv[kk]);
        o.x += e * vf.x;
        o.y += e * vf.y;
    }
    float inv = 1.f / den;
    __half2 ho = __floats2half2_rn(o.x * inv, o.y * inv);
    *((__half2*)(g_ao + (size_t)r * 256 + head * 32) + hl) = ho;
}

// ---------------- copy frame-8 query rows into g_x ----------------
__global__ void copy_frame8(const float* __restrict__ query)
{
    int blk = blockIdx.x;
    int b = blk >> 10, hw = blk & 1023;
    size_t idx = (((size_t)(b * 9 + 8) << 10) + hw) * 256 + threadIdx.x;
    g_x[idx] = query[idx];
}

// ---------------- temporal RoPE attention: 128 thr/seq, 2 heads/warp, half2 lanes ----------
__global__ void temporal_attn(const unsigned char* __restrict__ tmask)
{
    int s = blockIdx.x;                 // b*1024 + hw
    int w = threadIdx.x >> 5;
    int l = threadIdx.x & 31;
    int head = 2 * w + (l >> 4);
    int hl = l & 15;
    int b = s >> 10, hw = s & 1023;
    const float scale = 0.17677669529663687f;

    // rotary pair indices for dims 2hl, 2hl+1:  i = dim mod 16
    int i0 = 2 * (hl & 7), i1 = i0 + 1;
    float f0 = __powf(10000.f, -(float)i0 / 16.f);
    float f1 = __powf(10000.f, -(float)i1 / 16.f);
    bool x1side = (hl < 8);

    float2 q[9], k[9];
    uint32_t v[9];
#pragma unroll
    for (int t = 0; t < 9; t++) {
        size_t base = ((size_t)(b * 9 + t) * 1024 + hw) * 768 + head * 32;
        float2 qv = __half22float2(*((const __half2*)(g_qkv + base) + hl));
        float2 kv = __half22float2(*((const __half2*)(g_qkv + base + 256) + hl));
        v[t] = *(const uint32_t*)((const __half2*)(g_qkv + base + 512) + hl);
        float c0, s0, c1, s1;
        sincosf((float)t * f0, &s0, &c0);
        sincosf((float)t * f1, &s1, &c1);
        float2 qpart, kpart;
        qpart.x = __shfl_xor_sync(0xffffffffu, qv.x, 8);
        qpart.y = __shfl_xor_sync(0xffffffffu, qv.y, 8);
        kpart.x = __shfl_xor_sync(0xffffffffu, kv.x, 8);
        kpart.y = __shfl_xor_sync(0xffffffffu, kv.y, 8);
        if (x1side) {
            q[t].x = qv.x * c0 - qpart.x * s0;
            q[t].y = qv.y * c1 - qpart.y * s1;
            k[t].x = kv.x * c0 - kpart.x * s0;
            k[t].y = kv.y * c1 - kpart.y * s1;
        } else {
            q[t].x = qpart.x * s0 + qv.x * c0;
            q[t].y = qpart.y * s1 + qv.y * c1;
            k[t].x = kpart.x * s0 + kv.x * c0;
            k[t].y = kpart.y * s1 + kv.y * c1;
        }
    }
#pragma unroll
    for (int tq = 0; tq < 9; tq++) {
        float scr[9];
        float m = -1e30f;
#pragma unroll
        for (int tk = 0; tk < 9; tk++) {
            float d = hsum16(q[tq].x * k[tk].x + q[tq].y * k[tk].y) * scale;
            if (tmask[tq * 9 + tk]) d = -1e9f;
            scr[tk] = d;
            m = fmaxf(m, d);
        }
        float den = 0.f;
        float2 o = make_float2(0.f, 0.f);
#pragma unroll
        for (int tk = 0; tk < 9; tk++) {
            float e = __expf(scr[tk] - m);
            den += e;
            float2 vf = __half22float2(*(const __half2*)&v[tk]);
            o.x += e * vf.x;
            o.y += e * vf.y;
        }
        float inv = 1.f / den;
        size_t orow = (size_t)(b * 9 + tq) * 1024 + hw;
        __half2 ho = __floats2half2_rn(o.x * inv, o.y * inv);
        *((__half2*)(g_ao + orow * 256 + head * 32) + hl) = ho;
    }
}

// ---------------- CLS frame spatial mean + broadcast ----------------
__global__ void cls_avg()
{
    int b = blockIdx.x;
    int d = blockIdx.y * 32 + (threadIdx.x & 31);
    int part = threadIdx.x >> 5;
    float s = 0.f;
    for (int hw = part; hw < 1024; hw += 8)
        s += g_x2[(((size_t)b * 9) * 1024 + hw) * 256 + d];
    __shared__ float sm[8][32];
    sm[part][threadIdx.x & 31] = s;
    __syncthreads();
    if (part == 0) {
        float tot = 0.f;
#pragma unroll
        for (int p = 0; p < 8; p++) tot += sm[p][threadIdx.x & 31];
        sm[0][threadIdx.x & 31] = tot * (1.f / 1024.f);
    }
    __syncthreads();
    float avg = sm[0][threadIdx.x & 31];
    for (int hw = part; hw < 1024; hw += 8)
        g_x2[(((size_t)b * 9) * 1024 + hw) * 256 + d] = avg;
}

// ---------------- launch ----------------
extern "C" void kernel_launch(void* const* d_in, const int* in_sizes, int n_in,
                              void* d_out, int out_size)
{
    const float* query = (const float*)d_in[0];
    const unsigned char* tmask = (const unsigned char*)d_in[2];
    const float* sln_g = (const float*)d_in[3];
    const float* sln_b = (const float*)d_in[4];
    const float* s_wq = (const float*)d_in[5];
    const float* s_bq = (const float*)d_in[6];
    const float* s_wk = (const float*)d_in[7];
    const float* s_bk = (const float*)d_in[8];
    const float* s_wv = (const float*)d_in[9];
    const float* s_bv = (const float*)d_in[10];
    const float* s_wo = (const float*)d_in[11];
    const float* s_bo = (const float*)d_in[12];
    const float* tln_g = (const float*)d_in[13];
    const float* tln_b = (const float*)d_in[14];
    const float* t_wq = (const float*)d_in[15];
    const float* t_bq = (const float*)d_in[16];
    const float* t_wk = (const float*)d_in[17];
    const float* t_bk = (const float*)d_in[18];
    const float* t_wv = (const float*)d_in[19];
    const float* t_bv = (const float*)d_in[20];
    const float* t_wo = (const float*)d_in[21];
    const float* t_bo = (const float*)d_in[22];
    const float* mln_g = (const float*)d_in[23];
    const float* mln_b = (const float*)d_in[24];
    const float* w1 = (const float*)d_in[25];
    const float* b1 = (const float*)d_in[26];
    const float* w2 = (const float*)d_in[27];
    const float* b2 = (const float*)d_in[28];
    float* out = (float*)d_out;

    __half *p_ln, *p_ao, *p_h, *p_qkv, *p_wqkvT, *p_wT1, *p_wT2, *p_w1T, *p_w2T;
    float *p_x, *p_x2, *p_bqkv;
    cudaGetSymbolAddress((void**)&p_ln, g_ln);
    cudaGetSymbolAddress((void**)&p_qkv, g_qkv);
    cudaGetSymbolAddress((void**)&p_ao, g_ao);
    cudaGetSymbolAddress((void**)&p_x, g_x);
    cudaGetSymbolAddress((void**)&p_x2, g_x2);
    cudaGetSymbolAddress((void**)&p_h, g_h);
    cudaGetSymbolAddress((void**)&p_wqkvT, g_wqkvT);
    cudaGetSymbolAddress((void**)&p_bqkv, g_bqkv);
    cudaGetSymbolAddress((void**)&p_wT1, g_wT1);
    cudaGetSymbolAddress((void**)&p_wT2, g_wT2);
    cudaGetSymbolAddress((void**)&p_w1T, g_w1T);
    cudaGetSymbolAddress((void**)&p_w2T, g_w2T);

    cudaFuncSetAttribute(mma_gemm, cudaFuncAttributeMaxDynamicSharedMemorySize, GSMEM_BYTES);

    const int NOG = 1 << 30;

    // ---- weight prep ----
    pack_qkvT<<<768, 256>>>(s_wq, s_wk, s_wv, s_bq, s_bk, s_bv);
    transpose_w<<<256, 256>>>(s_wo, p_wT1, 256, 256);
    transpose_w<<<256, 256>>>(t_wo, p_wT2, 256, 256);
    transpose_w<<<1024, 256>>>(w1, p_w1T, 256, 1024);
    transpose_w<<<1024, 256>>>(w2, p_w2T, 1024, 256);

    // ---- spatial stage ----
    ln_kernel<<<ROWS_SP / 4, 128>>>(query, sln_g, sln_b, p_ln, ROWS_SP, 8192, 1024);
    mma_gemm<<<dim3(3, ROWS_SP / 128), 256, GSMEM_BYTES>>>(p_ln, p_wqkvT, p_bqkv, nullptr,
            nullptr, p_qkv, ROWS_SP, 768, 256, 4, NOG, 0);
    spatial_attn<<<ROWS_SP, 128>>>();
    mma_gemm<<<dim3(1, ROWS_SP / 128), 256, GSMEM_BYTES>>>(p_ao, p_wT1, s_bo, query,
            p_x, nullptr, ROWS_SP, 256, 256, 1, 8192, 1024);
    copy_frame8<<<4096, 256>>>(query);

    // ---- temporal stage ----
    ln_kernel<<<ROWS_T / 4, 128>>>(p_x, tln_g, tln_b, p_ln, ROWS_T, NOG, 0);
    pack_qkvT<<<768, 256>>>(t_wq, t_wk, t_wv, t_bq, t_bk, t_bv);
    mma_gemm<<<dim3(3, ROWS_T / 128), 256, GSMEM_BYTES>>>(p_ln, p_wqkvT, p_bqkv, nullptr,
            nullptr, p_qkv, ROWS_T, 768, 256, 4, NOG, 0);
    temporal_attn<<<Bq * HWc, 128>>>(tmask);
    mma_gemm<<<dim3(1, ROWS_T / 128), 256, GSMEM_BYTES>>>(p_ao, p_wT2, t_bo, p_x,
            p_x2, nullptr, ROWS_T, 256, 256, 1, NOG, 0);
    cls_avg<<<dim3(4, 8), 256>>>();

    // ---- MLP stage ----
    ln_kernel<<<ROWS_T / 4, 128>>>(p_x2, mln_g, mln_b, p_ln, ROWS_T, NOG, 0);
    mma_gemm<<<dim3(4, ROWS_T / 128), 256, GSMEM_BYTES>>>(p_ln, p_w1T, b1, nullptr,
            nullptr, p_h, ROWS_T, MLPD, 256, 2 | 4, NOG, 0);
    mma_gemm<<<dim3(1, ROWS_T / 128), 256, GSMEM_BYTES>>>(p_h, p_w2T, b2, p_x2,
            out, nullptr, ROWS_T, 256, 1024, 1, NOG, 0);
}

// round 10
// speedup vs baseline: 4.4489x; 1.1136x over previous
#include <cuda_runtime.h>
#include <cuda_fp16.h>
#include <math.h>
#include <stdint.h>

#define Bq 4
#define Tt 8
#define TQn 9
#define HWc 1024
#define Dm 256
#define MLPD 1024
#define ROWS_SP (Bq*Tt*HWc)   /* 32768 */
#define ROWS_T  (Bq*TQn*HWc)  /* 36864 */

// ---------------- scratch ----------------
__device__ __half g_ln  [(size_t)ROWS_T * Dm];
__device__ __half g_qkv [(size_t)ROWS_T * 768];
__device__ __half g_ao  [(size_t)ROWS_T * Dm];
__device__ float  g_x   [(size_t)ROWS_T * Dm];
__device__ float  g_x2  [(size_t)ROWS_T * Dm];
__device__ __half g_h   [(size_t)ROWS_T * MLPD];
__device__ __half g_wqkvT [768 * 256];    // spatial  [N=768,K=256]
__device__ __half g_wqkvT2[768 * 256];    // temporal
__device__ float  g_bqkv [768];
__device__ float  g_bqkv2[768];
__device__ __half g_wT1[256 * 256];       // s_wo^T [N,K]
__device__ __half g_wT2[256 * 256];       // t_wo^T
__device__ __half g_w1T[1024 * 256];      // w1^T [N,K]
__device__ __half g_w2T[256 * 1024];      // w2^T [N,K]

// ---------------- helpers ----------------
__device__ __forceinline__ float wsum(float v) {
#pragma unroll
    for (int o = 16; o; o >>= 1) v += __shfl_xor_sync(0xffffffffu, v, o);
    return v;
}
__device__ __forceinline__ float hsum16(float v) {
#pragma unroll
    for (int o = 8; o; o >>= 1) v += __shfl_xor_sync(0xffffffffu, v, o);
    return v;
}
__device__ __forceinline__ uint32_t smem_u32(const void* p) {
    uint32_t a;
    asm("{ .reg .u64 t; cvta.to.shared.u64 t, %1; cvt.u32.u64 %0, t; }" : "=r"(a) : "l"(p));
    return a;
}
#define CP_ASYNC16(dst, src) \
    asm volatile("cp.async.cg.shared.global [%0], [%1], 16;" :: "r"(dst), "l"(src))
#define CP_COMMIT() asm volatile("cp.async.commit_group;")
#define CP_WAIT0()  asm volatile("cp.async.wait_group 0;")
#define CP_WAIT1()  asm volatile("cp.async.wait_group 1;")

__device__ __forceinline__ void ldm_x4(uint32_t* r, uint32_t addr) {
    asm volatile("ldmatrix.sync.aligned.m8n8.x4.shared.b16 {%0,%1,%2,%3}, [%4];"
                 : "=r"(r[0]), "=r"(r[1]), "=r"(r[2]), "=r"(r[3]) : "r"(addr));
}
__device__ __forceinline__ void mma_f16(float* c, const uint32_t* a,
                                        uint32_t b0, uint32_t b1) {
    asm volatile(
        "mma.sync.aligned.m16n8k16.row.col.f32.f16.f16.f32 "
        "{%0,%1,%2,%3}, {%4,%5,%6,%7}, {%8,%9}, {%0,%1,%2,%3};"
        : "+f"(c[0]), "+f"(c[1]), "+f"(c[2]), "+f"(c[3])
        : "r"(a[0]), "r"(a[1]), "r"(a[2]), "r"(a[3]), "r"(b0), "r"(b1));
}

// ---------------- one-shot weight prep (all packs + transposes) ----------------
__global__ void prep_weights(
    const float* __restrict__ s_wq, const float* __restrict__ s_wk,
    const float* __restrict__ s_wv, const float* __restrict__ s_bq,
    const float* __restrict__ s_bk, const float* __restrict__ s_bv,
    const float* __restrict__ t_wq, const float* __restrict__ t_wk,
    const float* __restrict__ t_wv, const float* __restrict__ t_bq,
    const float* __restrict__ t_bk, const float* __restrict__ t_bv,
    const float* __restrict__ s_wo, const float* __restrict__ t_wo,
    const float* __restrict__ w1,   const float* __restrict__ w2)
{
    int blk = blockIdx.x;
    int tid = threadIdx.x;
    if (blk < 768) {                       // spatial QKV pack
        int i = blk * 256 + tid;
        int n = i >> 8, k = i & 255;
        const float* w = (n < 256) ? s_wq : (n < 512) ? s_wk : s_wv;
        g_wqkvT[i] = __float2half(w[k * 256 + (n & 255)]);
        if (i < 768)
            g_bqkv[i] = (i < 256) ? s_bq[i] : (i < 512) ? s_bk[i - 256] : s_bv[i - 512];
    } else if (blk < 1536) {               // temporal QKV pack
        int i = (blk - 768) * 256 + tid;
        int n = i >> 8, k = i & 255;
        const float* w = (n < 256) ? t_wq : (n < 512) ? t_wk : t_wv;
        g_wqkvT2[i] = __float2half(w[k * 256 + (n & 255)]);
        if (i < 768)
            g_bqkv2[i] = (i < 256) ? t_bq[i] : (i < 512) ? t_bk[i - 256] : t_bv[i - 512];
    } else if (blk < 1792) {               // s_wo^T (256x256)
        int i = (blk - 1536) * 256 + tid;
        int n = i >> 8, k = i & 255;
        g_wT1[i] = __float2half(s_wo[k * 256 + n]);
    } else if (blk < 2048) {               // t_wo^T
        int i = (blk - 1792) * 256 + tid;
        int n = i >> 8, k = i & 255;
        g_wT2[i] = __float2half(t_wo[k * 256 + n]);
    } else if (blk < 3072) {               // w1^T  [1024][256]
        int i = (blk - 2048) * 256 + tid;
        int n = i >> 8, k = i & 255;
        g_w1T[i] = __float2half(w1[k * 1024 + n]);
    } else {                               // w2^T  [256][1024]
        int i = (blk - 3072) * 256 + tid;
        int n = i >> 10, k = i & 1023;
        g_w2T[i] = __float2half(w2[k * 256 + n]);
    }
}

// ---------------- LayerNorm: fp32 in -> fp16 out ----------------
__global__ void ln_kernel(const float* __restrict__ X, const float* __restrict__ gam,
                          const float* __restrict__ bet, __half* __restrict__ Y,
                          int nrows, int grp, int skip)
{
    int row = blockIdx.x * 4 + (threadIdx.x >> 5);
    if (row >= nrows) return;
    int l = threadIdx.x & 31;
    size_t src = ((size_t)row + (size_t)(row / grp) * skip) * Dm;
    float4 v0 = *(const float4*)(X + src + 4 * l);
    float4 v1 = *(const float4*)(X + src + 128 + 4 * l);
    float s  = v0.x + v0.y + v0.z + v0.w + v1.x + v1.y + v1.z + v1.w;
    float sq = v0.x*v0.x + v0.y*v0.y + v0.z*v0.z + v0.w*v0.w
             + v1.x*v1.x + v1.y*v1.y + v1.z*v1.z + v1.w*v1.w;
    s = wsum(s); sq = wsum(sq);
    float mean = s * (1.f / 256.f);
    float var  = sq * (1.f / 256.f) - mean * mean;
    float rstd = rsqrtf(var + 1e-5f);
    float4 ga0 = *(const float4*)(gam + 4 * l), ga1 = *(const float4*)(gam + 128 + 4 * l);
    float4 be0 = *(const float4*)(bet + 4 * l), be1 = *(const float4*)(bet + 128 + 4 * l);
    __half2 h0 = __floats2half2_rn((v0.x - mean) * rstd * ga0.x + be0.x,
                                   (v0.y - mean) * rstd * ga0.y + be0.y);
    __half2 h1 = __floats2half2_rn((v0.z - mean) * rstd * ga0.z + be0.z,
                                   (v0.w - mean) * rstd * ga0.w + be0.w);
    __half2 h2 = __floats2half2_rn((v1.x - mean) * rstd * ga1.x + be1.x,
                                   (v1.y - mean) * rstd * ga1.y + be1.y);
    __half2 h3 = __floats2half2_rn((v1.z - mean) * rstd * ga1.z + be1.z,
                                   (v1.w - mean) * rstd * ga1.w + be1.w);
    uint2 u0 = { *(uint32_t*)&h0, *(uint32_t*)&h1 };
    uint2 u1 = { *(uint32_t*)&h2, *(uint32_t*)&h3 };
    *(uint2*)(Y + (size_t)row * Dm + 4 * l)       = u0;
    *(uint2*)(Y + (size_t)row * Dm + 128 + 4 * l) = u1;
}

// ---------------- fp16 mma.sync GEMM: CTA 128x128, warp 64x32, 3-stage, 2 CTA/SM -----------
// epi bit0: residual add (fp32), bit1: exact gelu, bit2: fp16 output to Ch (else fp32 to C)
#define ARS 80
#define A_BYTES (128 * ARS)            /* 10240 */
#define B_BYTES (128 * ARS)            /* 10240 */
#define STAGE_B (A_BYTES + B_BYTES)    /* 20480 */
#define GSMEM_BYTES (3 * STAGE_B)      /* 61440 */

__global__ __launch_bounds__(256, 2) void mma_gemm(
    const __half* __restrict__ A, const __half* __restrict__ BT,
    const float* __restrict__ bias, const float* __restrict__ res,
    float* __restrict__ C, __half* __restrict__ Ch,
    int M, int N, int K, int epi, int grp, int skip)
{
    extern __shared__ char smem[];
    uint32_t sbase = smem_u32(smem);

    int tid = threadIdx.x;
    int wid = tid >> 5, lane = tid & 31;
    int wm = wid >> 2, wn = wid & 3;           // 2 x 4 warps -> 64 x 32 tiles
    int gid = lane >> 2, tig = lane & 3;
    int i8 = lane & 7, bit0 = (lane >> 3) & 1, bit1 = lane >> 4;
    int bx = blockIdx.x, by = blockIdx.y;

    const __half* Abase = A  + (size_t)(by * 128) * K;
    const __half* Bbase = BT + (size_t)(bx * 128) * K;
    int nch = K >> 5;

    float acc[4][4][4];
#pragma unroll
    for (int i = 0; i < 4; i++)
#pragma unroll
        for (int j = 0; j < 4; j++)
#pragma unroll
            for (int c = 0; c < 4; c++) acc[i][j][c] = 0.f;

#pragma unroll
    for (int p = 0; p < 2; p++) {
        uint32_t stA = sbase + p * STAGE_B;
        uint32_t stB = stA + A_BYTES;
        const __half* Ag = Abase + p * 32;
        const __half* Bg = Bbase + p * 32;
#pragma unroll
        for (int i = 0; i < 2; i++) {
            int id = tid + i * 256, row = id >> 2, q = id & 3;
            CP_ASYNC16(stA + row * ARS + q * 16, Ag + (size_t)row * K + q * 8);
            CP_ASYNC16(stB + row * ARS + q * 16, Bg + (size_t)row * K + q * 8);
        }
        CP_COMMIT();
    }

    uint32_t aOff = (uint32_t)((wm * 64 + bit0 * 8 + i8) * ARS + bit1 * 16);
    uint32_t bOff = (uint32_t)(A_BYTES + (wn * 32 + bit1 * 8 + i8) * ARS + bit0 * 16);

    int st = 0;
    for (int ch = 0; ch < nch; ch++) {
        if (ch + 1 < nch) CP_WAIT1(); else CP_WAIT0();
        __syncthreads();
        if (ch + 2 < nch) {
            int ps = st + 2; if (ps >= 3) ps -= 3;
            uint32_t stA = sbase + ps * STAGE_B;
            uint32_t stB = stA + A_BYTES;
            const __half* Ag = Abase + (ch + 2) * 32;
            const __half* Bg = Bbase + (ch + 2) * 32;
#pragma unroll
            for (int i = 0; i < 2; i++) {
                int id = tid + i * 256, row = id >> 2, q = id & 3;
                CP_ASYNC16(stA + row * ARS + q * 16, Ag + (size_t)row * K + q * 8);
                CP_ASYNC16(stB + row * ARS + q * 16, Bg + (size_t)row * K + q * 8);
            }
            CP_COMMIT();
        }
        uint32_t stg = sbase + st * STAGE_B;
#pragma unroll
        for (int k16 = 0; k16 < 2; k16++) {
            uint32_t af[4][4], bf[2][4];
            uint32_t aA = stg + aOff + k16 * 32;
            uint32_t bA = stg + bOff + k16 * 32;
#pragma unroll
            for (int mt = 0; mt < 4; mt++) ldm_x4(af[mt], aA + mt * (16 * ARS));
#pragma unroll
            for (int p = 0; p < 2; p++)   ldm_x4(bf[p], bA + p * (16 * ARS));
#pragma unroll
            for (int mt = 0; mt < 4; mt++)
#pragma unroll
                for (int p = 0; p < 2; p++) {
                    mma_f16(acc[mt][2 * p],     af[mt], bf[p][0], bf[p][1]);
                    mma_f16(acc[mt][2 * p + 1], af[mt], bf[p][2], bf[p][3]);
                }
        }
        st++; if (st == 3) st = 0;
    }

    // ---- epilogue ----
#pragma unroll
    for (int mt = 0; mt < 4; mt++) {
#pragma unroll
        for (int half = 0; half < 2; half++) {
            int row = by * 128 + wm * 64 + mt * 16 + gid + half * 8;
            size_t crow = (size_t)row + (size_t)(row / grp) * skip;
#pragma unroll
            for (int n8 = 0; n8 < 4; n8++) {
                int cc = bx * 128 + wn * 32 + n8 * 8 + 2 * tig;
                float2 v;
                v.x = acc[mt][n8][2 * half + 0] + bias[cc];
                v.y = acc[mt][n8][2 * half + 1] + bias[cc + 1];
                size_t base = crow * (size_t)N + cc;
                if (epi & 1) {
                    float2 rr = *(const float2*)(res + base);
                    v.x += rr.x; v.y += rr.y;
                }
                if (epi & 2) {
                    v.x = 0.5f * v.x * (1.0f + erff(v.x * 0.7071067811865476f));
                    v.y = 0.5f * v.y * (1.0f + erff(v.y * 0.7071067811865476f));
                }
                if (epi & 4) {
                    __half2 h = __floats2half2_rn(v.x, v.y);
                    *(__half2*)(Ch + base) = h;
                } else {
                    *(float2*)(C + base) = v;
                }
            }
        }
    }
}

// ---------------- spatial 3x3 windowed attention: 128 thr/token, 2 heads/warp ----------
__global__ void spatial_attn()
{
    int r = blockIdx.x;
    int w = threadIdx.x >> 5;
    int l = threadIdx.x & 31;
    int head = 2 * w + (l >> 4);
    int hl = l & 15;
    int bt = r >> 10, n = r & 1023;
    int y = n >> 5, x = n & 31;
    const float scale = 0.17677669529663687f;

    const __half2* qp = (const __half2*)(g_qkv + (size_t)r * 768 + head * 32) + hl;
    float2 q = __half22float2(*qp);

    float sc[9];
    uint32_t vv[9];
    bool ok[9];
#pragma unroll
    for (int kk = 0; kk < 9; kk++) {
        int ny = y + kk / 3 - 1, nx = x + kk % 3 - 1;
        bool valid = ((unsigned)ny < 32u) && ((unsigned)nx < 32u);
        ok[kk] = valid;
        int rn = valid ? ((bt << 10) + (ny << 5) + nx) : r;
        const __half2* kp = (const __half2*)(g_qkv + (size_t)rn * 768 + 256 + head * 32) + hl;
        float2 kv = __half22float2(*kp);
        vv[kk] = *(const uint32_t*)((const __half2*)(g_qkv + (size_t)rn * 768 + 512 + head * 32) + hl);
        float d = hsum16(q.x * kv.x + q.y * kv.y) * scale;
        sc[kk] = valid ? d : -1e30f;
    }
    float m = sc[0];
#pragma unroll
    for (int kk = 1; kk < 9; kk++) m = fmaxf(m, sc[kk]);
    float den = 0.f;
    float2 o = make_float2(0.f, 0.f);
#pragma unroll
    for (int kk = 0; kk < 9; kk++) {
        float e = ok[kk] ? __expf(sc[kk] - m) : 0.f;
        den += e;
        float2 vf = __half22float2(*(const __half2*)&vv[kk]);
        o.x += e * vf.x;
        o.y += e * vf.y;
    }
    float inv = 1.f / den;
    __half2 ho = __floats2half2_rn(o.x * inv, o.y * inv);
    *((__half2*)(g_ao + (size_t)r * 256 + head * 32) + hl) = ho;
}

// ---------------- copy frame-8 query rows into g_x ----------------
__global__ void copy_frame8(const float* __restrict__ query)
{
    int blk = blockIdx.x;
    int b = blk >> 10, hw = blk & 1023;
    size_t idx = (((size_t)(b * 9 + 8) << 10) + hw) * 256 + threadIdx.x;
    g_x[idx] = query[idx];
}

// ---------------- temporal RoPE attention: 128 thr/seq, 2 heads/warp ----------
__global__ void temporal_attn(const unsigned char* __restrict__ tmask)
{
    int s = blockIdx.x;
    int w = threadIdx.x >> 5;
    int l = threadIdx.x & 31;
    int head = 2 * w + (l >> 4);
    int hl = l & 15;
    int b = s >> 10, hw = s & 1023;
    const float scale = 0.17677669529663687f;

    int i0 = 2 * (hl & 7), i1 = i0 + 1;
    float f0 = __powf(10000.f, -(float)i0 / 16.f);
    float f1 = __powf(10000.f, -(float)i1 / 16.f);
    bool x1side = (hl < 8);

    float2 q[9], k[9];
    uint32_t v[9];
#pragma unroll
    for (int t = 0; t < 9; t++) {
        size_t base = ((size_t)(b * 9 + t) * 1024 + hw) * 768 + head * 32;
        float2 qv = __half22float2(*((const __half2*)(g_qkv + base) + hl));
        float2 kv = __half22float2(*((const __half2*)(g_qkv + base + 256) + hl));
        v[t] = *(const uint32_t*)((const __half2*)(g_qkv + base + 512) + hl);
        float c0, s0, c1, s1;
        sincosf((float)t * f0, &s0, &c0);
        sincosf((float)t * f1, &s1, &c1);
        float2 qpart, kpart;
        qpart.x = __shfl_xor_sync(0xffffffffu, qv.x, 8);
        qpart.y = __shfl_xor_sync(0xffffffffu, qv.y, 8);
        kpart.x = __shfl_xor_sync(0xffffffffu, kv.x, 8);
        kpart.y = __shfl_xor_sync(0xffffffffu, kv.y, 8);
        if (x1side) {
            q[t].x = qv.x * c0 - qpart.x * s0;
            q[t].y = qv.y * c1 - qpart.y * s1;
            k[t].x = kv.x * c0 - kpart.x * s0;
            k[t].y = kv.y * c1 - kpart.y * s1;
        } else {
            q[t].x = qpart.x * s0 + qv.x * c0;
            q[t].y = qpart.y * s1 + qv.y * c1;
            k[t].x = kpart.x * s0 + kv.x * c0;
            k[t].y = kpart.y * s1 + kv.y * c1;
        }
    }
#pragma unroll
    for (int tq = 0; tq < 9; tq++) {
        float scr[9];
        float m = -1e30f;
#pragma unroll
        for (int tk = 0; tk < 9; tk++) {
            float d = hsum16(q[tq].x * k[tk].x + q[tq].y * k[tk].y) * scale;
            if (tmask[tq * 9 + tk]) d = -1e9f;
            scr[tk] = d;
            m = fmaxf(m, d);
        }
        float den = 0.f;
        float2 o = make_float2(0.f, 0.f);
#pragma unroll
        for (int tk = 0; tk < 9; tk++) {
            float e = __expf(scr[tk] - m);
            den += e;
            float2 vf = __half22float2(*(const __half2*)&v[tk]);
            o.x += e * vf.x;
            o.y += e * vf.y;
        }
        float inv = 1.f / den;
        size_t orow = (size_t)(b * 9 + tq) * 1024 + hw;
        __half2 ho = __floats2half2_rn(o.x * inv, o.y * inv);
        *((__half2*)(g_ao + orow * 256 + head * 32) + hl) = ho;
    }
}

// ---------------- CLS frame spatial mean + broadcast ----------------
__global__ void cls_avg()
{
    int b = blockIdx.x;
    int d = blockIdx.y * 32 + (threadIdx.x & 31);
    int part = threadIdx.x >> 5;
    float s = 0.f;
    for (int hw = part; hw < 1024; hw += 8)
        s += g_x2[(((size_t)b * 9) * 1024 + hw) * 256 + d];
    __shared__ float sm[8][32];
    sm[part][threadIdx.x & 31] = s;
    __syncthreads();
    if (part == 0) {
        float tot = 0.f;
#pragma unroll
        for (int p = 0; p < 8; p++) tot += sm[p][threadIdx.x & 31];
        sm[0][threadIdx.x & 31] = tot * (1.f / 1024.f);
    }
    __syncthreads();
    float avg = sm[0][threadIdx.x & 31];
    for (int hw = part; hw < 1024; hw += 8)
        g_x2[(((size_t)b * 9) * 1024 + hw) * 256 + d] = avg;
}

// ---------------- launch ----------------
extern "C" void kernel_launch(void* const* d_in, const int* in_sizes, int n_in,
                              void* d_out, int out_size)
{
    const float* query = (const float*)d_in[0];
    const unsigned char* tmask = (const unsigned char*)d_in[2];
    const float* sln_g = (const float*)d_in[3];
    const float* sln_b = (const float*)d_in[4];
    const float* s_wq = (const float*)d_in[5];
    const float* s_bq = (const float*)d_in[6];
    const float* s_wk = (const float*)d_in[7];
    const float* s_bk = (const float*)d_in[8];
    const float* s_wv = (const float*)d_in[9];
    const float* s_bv = (const float*)d_in[10];
    const float* s_wo = (const float*)d_in[11];
    const float* s_bo = (const float*)d_in[12];
    const float* tln_g = (const float*)d_in[13];
    const float* tln_b = (const float*)d_in[14];
    const float* t_wq = (const float*)d_in[15];
    const float* t_bq = (const float*)d_in[16];
    const float* t_wk = (const float*)d_in[17];
    const float* t_bk = (const float*)d_in[18];
    const float* t_wv = (const float*)d_in[19];
    const float* t_bv = (const float*)d_in[20];
    const float* t_wo = (const float*)d_in[21];
    const float* t_bo = (const float*)d_in[22];
    const float* mln_g = (const float*)d_in[23];
    const float* mln_b = (const float*)d_in[24];
    const float* w1 = (const float*)d_in[25];
    const float* b1 = (const float*)d_in[26];
    const float* w2 = (const float*)d_in[27];
    const float* b2 = (const float*)d_in[28];
    float* out = (float*)d_out;

    __half *p_ln, *p_ao, *p_h, *p_qkv, *p_wqkvT, *p_wqkvT2, *p_wT1, *p_wT2, *p_w1T, *p_w2T;
    float *p_x, *p_x2, *p_bqkv, *p_bqkv2;
    cudaGetSymbolAddress((void**)&p_ln, g_ln);
    cudaGetSymbolAddress((void**)&p_qkv, g_qkv);
    cudaGetSymbolAddress((void**)&p_ao, g_ao);
    cudaGetSymbolAddress((void**)&p_x, g_x);
    cudaGetSymbolAddress((void**)&p_x2, g_x2);
    cudaGetSymbolAddress((void**)&p_h, g_h);
    cudaGetSymbolAddress((void**)&p_wqkvT, g_wqkvT);
    cudaGetSymbolAddress((void**)&p_wqkvT2, g_wqkvT2);
    cudaGetSymbolAddress((void**)&p_bqkv, g_bqkv);
    cudaGetSymbolAddress((void**)&p_bqkv2, g_bqkv2);
    cudaGetSymbolAddress((void**)&p_wT1, g_wT1);
    cudaGetSymbolAddress((void**)&p_wT2, g_wT2);
    cudaGetSymbolAddress((void**)&p_w1T, g_w1T);
    cudaGetSymbolAddress((void**)&p_w2T, g_w2T);

    cudaFuncSetAttribute(mma_gemm, cudaFuncAttributeMaxDynamicSharedMemorySize, GSMEM_BYTES);

    const int NOG = 1 << 30;

    // ---- weight prep (single launch, off critical path after LN) ----
    prep_weights<<<4096, 256>>>(s_wq, s_wk, s_wv, s_bq, s_bk, s_bv,
                                t_wq, t_wk, t_wv, t_bq, t_bk, t_bv,
                                s_wo, t_wo, w1, w2);

    // ---- spatial stage ----
    ln_kernel<<<ROWS_SP / 4, 128>>>(query, sln_g, sln_b, p_ln, ROWS_SP, 8192, 1024);
    mma_gemm<<<dim3(6, ROWS_SP / 128), 256, GSMEM_BYTES>>>(p_ln, p_wqkvT, p_bqkv, nullptr,
            nullptr, p_qkv, ROWS_SP, 768, 256, 4, NOG, 0);
    spatial_attn<<<ROWS_SP, 128>>>();
    mma_gemm<<<dim3(2, ROWS_SP / 128), 256, GSMEM_BYTES>>>(p_ao, p_wT1, s_bo, query,
            p_x, nullptr, ROWS_SP, 256, 256, 1, 8192, 1024);
    copy_frame8<<<4096, 256>>>(query);

    // ---- temporal stage ----
    ln_kernel<<<ROWS_T / 4, 128>>>(p_x, tln_g, tln_b, p_ln, ROWS_T, NOG, 0);
    mma_gemm<<<dim3(6, ROWS_T / 128), 256, GSMEM_BYTES>>>(p_ln, p_wqkvT2, p_bqkv2, nullptr,
            nullptr, p_qkv, ROWS_T, 768, 256, 4, NOG, 0);
    temporal_attn<<<Bq * HWc, 128>>>(tmask);
    mma_gemm<<<dim3(2, ROWS_T / 128), 256, GSMEM_BYTES>>>(p_ao, p_wT2, t_bo, p_x,
            p_x2, nullptr, ROWS_T, 256, 256, 1, NOG, 0);
    cls_avg<<<dim3(4, 8), 256>>>();

    // ---- MLP stage ----
    ln_kernel<<<ROWS_T / 4, 128>>>(p_x2, mln_g, mln_b, p_ln, ROWS_T, NOG, 0);
    mma_gemm<<<dim3(8, ROWS_T / 128), 256, GSMEM_BYTES>>>(p_ln, p_w1T, b1, nullptr,
            nullptr, p_h, ROWS_T, MLPD, 256, 2 | 4, NOG, 0);
    mma_gemm<<<dim3(2, ROWS_T / 128), 256, GSMEM_BYTES>>>(p_h, p_w2T, b2, p_x2,
            out, nullptr, ROWS_T, 256, 1024, 1, NOG, 0);
}

// round 13
// speedup vs baseline: 4.4992x; 1.0113x over previous
#include <cuda_runtime.h>
#include <cuda_fp16.h>
#include <math.h>
#include <stdint.h>

#define Bq 4
#define Tt 8
#define TQn 9
#define HWc 1024
#define Dm 256
#define MLPD 1024
#define ROWS_SP (Bq*Tt*HWc)   /* 32768 */
#define ROWS_T  (Bq*TQn*HWc)  /* 36864 */

// ---------------- scratch ----------------
__device__ __half g_ln  [(size_t)ROWS_T * Dm];
__device__ __half g_qkv [(size_t)ROWS_T * 768];
__device__ __half g_ao  [(size_t)ROWS_T * Dm];
__device__ float  g_x   [(size_t)ROWS_T * Dm];
__device__ float  g_x2  [(size_t)ROWS_T * Dm];
__device__ __half g_h   [(size_t)ROWS_T * MLPD];
__device__ __half g_wqkvT [768 * 256];
__device__ __half g_wqkvT2[768 * 256];
__device__ float  g_bqkv [768];
__device__ float  g_bqkv2[768];
__device__ __half g_wT1[256 * 256];
__device__ __half g_wT2[256 * 256];
__device__ __half g_w1T[1024 * 256];
__device__ __half g_w2T[256 * 1024];

// ---------------- helpers ----------------
__device__ __forceinline__ float wsum(float v) {
#pragma unroll
    for (int o = 16; o; o >>= 1) v += __shfl_xor_sync(0xffffffffu, v, o);
    return v;
}
__device__ __forceinline__ float hsum16(float v) {
#pragma unroll
    for (int o = 8; o; o >>= 1) v += __shfl_xor_sync(0xffffffffu, v, o);
    return v;
}
__device__ __forceinline__ uint32_t smem_u32(const void* p) {
    uint32_t a;
    asm("{ .reg .u64 t; cvta.to.shared.u64 t, %1; cvt.u32.u64 %0, t; }" : "=r"(a) : "l"(p));
    return a;
}
#define CP_ASYNC16(dst, src) \
    asm volatile("cp.async.cg.shared.global [%0], [%1], 16;" :: "r"(dst), "l"(src))
#define CP_COMMIT() asm volatile("cp.async.commit_group;")
#define CP_WAIT0()  asm volatile("cp.async.wait_group 0;")
#define CP_WAIT1()  asm volatile("cp.async.wait_group 1;")

__device__ __forceinline__ void ldm_x4(uint32_t* r, uint32_t addr) {
    asm volatile("ldmatrix.sync.aligned.m8n8.x4.shared.b16 {%0,%1,%2,%3}, [%4];"
                 : "=r"(r[0]), "=r"(r[1]), "=r"(r[2]), "=r"(r[3]) : "r"(addr));
}
__device__ __forceinline__ void mma_f16(float* c, const uint32_t* a,
                                        uint32_t b0, uint32_t b1) {
    asm volatile(
        "mma.sync.aligned.m16n8k16.row.col.f32.f16.f16.f32 "
        "{%0,%1,%2,%3}, {%4,%5,%6,%7}, {%8,%9}, {%0,%1,%2,%3};"
        : "+f"(c[0]), "+f"(c[1]), "+f"(c[2]), "+f"(c[3])
        : "r"(a[0]), "r"(a[1]), "r"(a[2]), "r"(a[3]), "r"(b0), "r"(b1));
}
__device__ __forceinline__ __half2 u2h2(uint32_t u) { return *(__half2*)&u; }

// ---------------- one-shot weight prep ----------------
__global__ void prep_weights(
    const float* __restrict__ s_wq, const float* __restrict__ s_wk,
    const float* __restrict__ s_wv, const float* __restrict__ s_bq,
    const float* __restrict__ s_bk, const float* __restrict__ s_bv,
    const float* __restrict__ t_wq, const float* __restrict__ t_wk,
    const float* __restrict__ t_wv, const float* __restrict__ t_bq,
    const float* __restrict__ t_bk, const float* __restrict__ t_bv,
    const float* __restrict__ s_wo, const float* __restrict__ t_wo,
    const float* __restrict__ w1,   const float* __restrict__ w2)
{
    int blk = blockIdx.x;
    int tid = threadIdx.x;
    if (blk < 768) {
        int i = blk * 256 + tid;
        int n = i >> 8, k = i & 255;
        const float* w = (n < 256) ? s_wq : (n < 512) ? s_wk : s_wv;
        g_wqkvT[i] = __float2half(w[k * 256 + (n & 255)]);
        if (i < 768)
            g_bqkv[i] = (i < 256) ? s_bq[i] : (i < 512) ? s_bk[i - 256] : s_bv[i - 512];
    } else if (blk < 1536) {
        int i = (blk - 768) * 256 + tid;
        int n = i >> 8, k = i & 255;
        const float* w = (n < 256) ? t_wq : (n < 512) ? t_wk : t_wv;
        g_wqkvT2[i] = __float2half(w[k * 256 + (n & 255)]);
        if (i < 768)
            g_bqkv2[i] = (i < 256) ? t_bq[i] : (i < 512) ? t_bk[i - 256] : t_bv[i - 512];
    } else if (blk < 1792) {
        int i = (blk - 1536) * 256 + tid;
        int n = i >> 8, k = i & 255;
        g_wT1[i] = __float2half(s_wo[k * 256 + n]);
    } else if (blk < 2048) {
        int i = (blk - 1792) * 256 + tid;
        int n = i >> 8, k = i & 255;
        g_wT2[i] = __float2half(t_wo[k * 256 + n]);
    } else if (blk < 3072) {
        int i = (blk - 2048) * 256 + tid;
        int n = i >> 8, k = i & 255;
        g_w1T[i] = __float2half(w1[k * 1024 + n]);
    } else {
        int i = (blk - 3072) * 256 + tid;
        int n = i >> 10, k = i & 1023;
        g_w2T[i] = __float2half(w2[k * 256 + n]);
    }
}

// ---------------- LayerNorm: fp32 in -> fp16 out ----------------
__global__ void ln_kernel(const float* __restrict__ X, const float* __restrict__ gam,
                          const float* __restrict__ bet, __half* __restrict__ Y,
                          int nrows, int grp, int skip)
{
    int row = blockIdx.x * 4 + (threadIdx.x >> 5);
    if (row >= nrows) return;
    int l = threadIdx.x & 31;
    size_t src = ((size_t)row + (size_t)(row / grp) * skip) * Dm;
    float4 v0 = *(const float4*)(X + src + 4 * l);
    float4 v1 = *(const float4*)(X + src + 128 + 4 * l);
    float s  = v0.x + v0.y + v0.z + v0.w + v1.x + v1.y + v1.z + v1.w;
    float sq = v0.x*v0.x + v0.y*v0.y + v0.z*v0.z + v0.w*v0.w
             + v1.x*v1.x + v1.y*v1.y + v1.z*v1.z + v1.w*v1.w;
    s = wsum(s); sq = wsum(sq);
    float mean = s * (1.f / 256.f);
    float var  = sq * (1.f / 256.f) - mean * mean;
    float rstd = rsqrtf(var + 1e-5f);
    float4 ga0 = *(const float4*)(gam + 4 * l), ga1 = *(const float4*)(gam + 128 + 4 * l);
    float4 be0 = *(const float4*)(bet + 4 * l), be1 = *(const float4*)(bet + 128 + 4 * l);
    __half2 h0 = __floats2half2_rn((v0.x - mean) * rstd * ga0.x + be0.x,
                                   (v0.y - mean) * rstd * ga0.y + be0.y);
    __half2 h1 = __floats2half2_rn((v0.z - mean) * rstd * ga0.z + be0.z,
                                   (v0.w - mean) * rstd * ga0.w + be0.w);
    __half2 h2 = __floats2half2_rn((v1.x - mean) * rstd * ga1.x + be1.x,
                                   (v1.y - mean) * rstd * ga1.y + be1.y);
    __half2 h3 = __floats2half2_rn((v1.z - mean) * rstd * ga1.z + be1.z,
                                   (v1.w - mean) * rstd * ga1.w + be1.w);
    uint2 u0 = { *(uint32_t*)&h0, *(uint32_t*)&h1 };
    uint2 u1 = { *(uint32_t*)&h2, *(uint32_t*)&h3 };
    *(uint2*)(Y + (size_t)row * Dm + 4 * l)       = u0;
    *(uint2*)(Y + (size_t)row * Dm + 128 + 4 * l) = u1;
}

// ---------------- fp16 mma.sync GEMM: CTA 128x128, warp 64x32, 3-stage, 2 CTA/SM -----------
#define ARS 80
#define A_BYTES (128 * ARS)
#define B_BYTES (128 * ARS)
#define STAGE_B (A_BYTES + B_BYTES)
#define GSMEM_BYTES (3 * STAGE_B)

__global__ __launch_bounds__(256, 2) void mma_gemm(
    const __half* __restrict__ A, const __half* __restrict__ BT,
    const float* __restrict__ bias, const float* __restrict__ res,
    float* __restrict__ C, __half* __restrict__ Ch,
    int M, int N, int K, int epi, int grp, int skip)
{
    extern __shared__ char smem[];
    uint32_t sbase = smem_u32(smem);

    int tid = threadIdx.x;
    int wid = tid >> 5, lane = tid & 31;
    int wm = wid >> 2, wn = wid & 3;
    int gid = lane >> 2, tig = lane & 3;
    int i8 = lane & 7, bit0 = (lane >> 3) & 1, bit1 = lane >> 4;
    int bx = blockIdx.x, by = blockIdx.y;

    const __half* Abase = A  + (size_t)(by * 128) * K;
    const __half* Bbase = BT + (size_t)(bx * 128) * K;
    int nch = K >> 5;

    float acc[4][4][4];
#pragma unroll
    for (int i = 0; i < 4; i++)
#pragma unroll
        for (int j = 0; j < 4; j++)
#pragma unroll
            for (int c = 0; c < 4; c++) acc[i][j][c] = 0.f;

#pragma unroll
    for (int p = 0; p < 2; p++) {
        uint32_t stA = sbase + p * STAGE_B;
        uint32_t stB = stA + A_BYTES;
        const __half* Ag = Abase + p * 32;
        const __half* Bg = Bbase + p * 32;
#pragma unroll
        for (int i = 0; i < 2; i++) {
            int id = tid + i * 256, row = id >> 2, q = id & 3;
            CP_ASYNC16(stA + row * ARS + q * 16, Ag + (size_t)row * K + q * 8);
            CP_ASYNC16(stB + row * ARS + q * 16, Bg + (size_t)row * K + q * 8);
        }
        CP_COMMIT();
    }

    uint32_t aOff = (uint32_t)((wm * 64 + bit0 * 8 + i8) * ARS + bit1 * 16);
    uint32_t bOff = (uint32_t)(A_BYTES + (wn * 32 + bit1 * 8 + i8) * ARS + bit0 * 16);

    int st = 0;
    for (int ch = 0; ch < nch; ch++) {
        if (ch + 1 < nch) CP_WAIT1(); else CP_WAIT0();
        __syncthreads();
        if (ch + 2 < nch) {
            int ps = st + 2; if (ps >= 3) ps -= 3;
            uint32_t stA = sbase + ps * STAGE_B;
            uint32_t stB = stA + A_BYTES;
            const __half* Ag = Abase + (ch + 2) * 32;
            const __half* Bg = Bbase + (ch + 2) * 32;
#pragma unroll
            for (int i = 0; i < 2; i++) {
                int id = tid + i * 256, row = id >> 2, q = id & 3;
                CP_ASYNC16(stA + row * ARS + q * 16, Ag + (size_t)row * K + q * 8);
                CP_ASYNC16(stB + row * ARS + q * 16, Bg + (size_t)row * K + q * 8);
            }
            CP_COMMIT();
        }
        uint32_t stg = sbase + st * STAGE_B;
#pragma unroll
        for (int k16 = 0; k16 < 2; k16++) {
            uint32_t af[4][4], bf[2][4];
            uint32_t aA = stg + aOff + k16 * 32;
            uint32_t bA = stg + bOff + k16 * 32;
#pragma unroll
            for (int mt = 0; mt < 4; mt++) ldm_x4(af[mt], aA + mt * (16 * ARS));
#pragma unroll
            for (int p = 0; p < 2; p++)   ldm_x4(bf[p], bA + p * (16 * ARS));
#pragma unroll
            for (int mt = 0; mt < 4; mt++)
#pragma unroll
                for (int p = 0; p < 2; p++) {
                    mma_f16(acc[mt][2 * p],     af[mt], bf[p][0], bf[p][1]);
                    mma_f16(acc[mt][2 * p + 1], af[mt], bf[p][2], bf[p][3]);
                }
        }
        st++; if (st == 3) st = 0;
    }

    // ---- epilogue ----
#pragma unroll
    for (int mt = 0; mt < 4; mt++) {
#pragma unroll
        for (int half = 0; half < 2; half++) {
            int row = by * 128 + wm * 64 + mt * 16 + gid + half * 8;
            size_t crow = (size_t)row + (size_t)(row / grp) * skip;
#pragma unroll
            for (int n8 = 0; n8 < 4; n8++) {
                int cc = bx * 128 + wn * 32 + n8 * 8 + 2 * tig;
                float2 v;
                v.x = acc[mt][n8][2 * half + 0] + bias[cc];
                v.y = acc[mt][n8][2 * half + 1] + bias[cc + 1];
                size_t base = crow * (size_t)N + cc;
                if (epi & 1) {
                    float2 rr = *(const float2*)(res + base);
                    v.x += rr.x; v.y += rr.y;
                }
                if (epi & 2) {
                    v.x = 0.5f * v.x * (1.0f + erff(v.x * 0.7071067811865476f));
                    v.y = 0.5f * v.y * (1.0f + erff(v.y * 0.7071067811865476f));
                }
                if (epi & 4) {
                    __half2 h = __floats2half2_rn(v.x, v.y);
                    *(__half2*)(Ch + base) = h;
                } else {
                    *(float2*)(C + base) = v;
                }
            }
        }
    }
}

// ---------------- spatial 3x3 windowed attention: 1 thread = (token, head) -----------------
// g = r*8 + h ; adjacent lanes = adjacent heads -> contiguous 512B rows per 8 lanes.
__global__ __launch_bounds__(256) void spatial_attn()
{
    int g = blockIdx.x * 256 + threadIdx.x;
    int r = g >> 3, h = g & 7;
    int bt = r >> 10, n = r & 1023;
    int y = n >> 5, x = n & 31;
    const float scale = 0.17677669529663687f;

    // load q (32 halfs = 4 x uint4)
    const uint4* qp = (const uint4*)(g_qkv + (size_t)r * 768 + h * 32);
    uint4 qv[4];
#pragma unroll
    for (int i = 0; i < 4; i++) qv[i] = qp[i];

    float sc[9];
    int rn9[9];
#pragma unroll
    for (int kk = 0; kk < 9; kk++) {
        int ny = y + kk / 3 - 1, nx = x + kk % 3 - 1;
        bool valid = ((unsigned)ny < 32u) && ((unsigned)nx < 32u);
        int rn = valid ? ((bt << 10) + (ny << 5) + nx) : r;
        rn9[kk] = rn;
        const uint4* kp = (const uint4*)(g_qkv + (size_t)rn * 768 + 256 + h * 32);
        float d = 0.f;
#pragma unroll
        for (int i = 0; i < 4; i++) {
            uint4 kv = kp[i];
            __half2 a = __hmul2(u2h2(qv[i].x), u2h2(kv.x));
            a = __hfma2(u2h2(qv[i].y), u2h2(kv.y), a);
            a = __hfma2(u2h2(qv[i].z), u2h2(kv.z), a);
            a = __hfma2(u2h2(qv[i].w), u2h2(kv.w), a);
            float2 f = __half22float2(a);
            d += f.x + f.y;
        }
        sc[kk] = valid ? d * scale : -1e30f;
    }
    float m = sc[0];
#pragma unroll
    for (int kk = 1; kk < 9; kk++) m = fmaxf(m, sc[kk]);

    __half2 o[16];
#pragma unroll
    for (int i = 0; i < 16; i++) o[i] = __float2half2_rn(0.f);
    float den = 0.f;
#pragma unroll
    for (int kk = 0; kk < 9; kk++) {
        float e = __expf(sc[kk] - m);
        den += e;
        __half2 e2 = __float2half2_rn(e);
        const uint4* vp = (const uint4*)(g_qkv + (size_t)rn9[kk] * 768 + 512 + h * 32);
#pragma unroll
        for (int i = 0; i < 4; i++) {
            uint4 vv = vp[i];
            o[4 * i + 0] = __hfma2(e2, u2h2(vv.x), o[4 * i + 0]);
            o[4 * i + 1] = __hfma2(e2, u2h2(vv.y), o[4 * i + 1]);
            o[4 * i + 2] = __hfma2(e2, u2h2(vv.z), o[4 * i + 2]);
            o[4 * i + 3] = __hfma2(e2, u2h2(vv.w), o[4 * i + 3]);
        }
    }
    float inv = 1.f / den;
    uint4* op = (uint4*)(g_ao + (size_t)r * 256 + h * 32);
#pragma unroll
    for (int i = 0; i < 4; i++) {
        uint4 outv;
        uint32_t* w = &outv.x;
#pragma unroll
        for (int j = 0; j < 4; j++) {
            float2 f = __half22float2(o[4 * i + j]);
            __half2 hh = __floats2half2_rn(f.x * inv, f.y * inv);
            w[j] = *(uint32_t*)&hh;
        }
        op[i] = outv;
    }
}

// ---------------- copy frame-8 query rows into g_x ----------------
__global__ void copy_frame8(const float* __restrict__ query)
{
    int blk = blockIdx.x;
    int b = blk >> 10, hw = blk & 1023;
    size_t idx = (((size_t)(b * 9 + 8) << 10) + hw) * 256 + threadIdx.x;
    g_x[idx] = query[idx];
}

// ---------------- temporal RoPE attention: 128 thr/seq, 2 heads/warp ----------
__global__ void temporal_attn(const unsigned char* __restrict__ tmask)
{
    int s = blockIdx.x;
    int w = threadIdx.x >> 5;
    int l = threadIdx.x & 31;
    int head = 2 * w + (l >> 4);
    int hl = l & 15;
    int b = s >> 10, hw = s & 1023;
    const float scale = 0.17677669529663687f;

    int i0 = 2 * (hl & 7), i1 = i0 + 1;
    float f0 = __powf(10000.f, -(float)i0 / 16.f);
    float f1 = __powf(10000.f, -(float)i1 / 16.f);
    bool x1side = (hl < 8);

    float2 q[9], k[9];
    uint32_t v[9];
#pragma unroll
    for (int t = 0; t < 9; t++) {
        size_t base = ((size_t)(b * 9 + t) * 1024 + hw) * 768 + head * 32;
        float2 qv = __half22float2(*((const __half2*)(g_qkv + base) + hl));
        float2 kv = __half22float2(*((const __half2*)(g_qkv + base + 256) + hl));
        v[t] = *(const uint32_t*)((const __half2*)(g_qkv + base + 512) + hl);
        float c0, s0, c1, s1;
        sincosf((float)t * f0, &s0, &c0);
        sincosf((float)t * f1, &s1, &c1);
        float2 qpart, kpart;
        qpart.x = __shfl_xor_sync(0xffffffffu, qv.x, 8);
        qpart.y = __shfl_xor_sync(0xffffffffu, qv.y, 8);
        kpart.x = __shfl_xor_sync(0xffffffffu, kv.x, 8);
        kpart.y = __shfl_xor_sync(0xffffffffu, kv.y, 8);
        if (x1side) {
            q[t].x = qv.x * c0 - qpart.x * s0;
            q[t].y = qv.y * c1 - qpart.y * s1;
            k[t].x = kv.x * c0 - kpart.x * s0;
            k[t].y = kv.y * c1 - kpart.y * s1;
        } else {
            q[t].x = qpart.x * s0 + qv.x * c0;
            q[t].y = qpart.y * s1 + qv.y * c1;
            k[t].x = kpart.x * s0 + kv.x * c0;
            k[t].y = kpart.y * s1 + kv.y * c1;
        }
    }
#pragma unroll
    for (int tq = 0; tq < 9; tq++) {
        float scr[9];
        float m = -1e30f;
#pragma unroll
        for (int tk = 0; tk < 9; tk++) {
            float d = hsum16(q[tq].x * k[tk].x + q[tq].y * k[tk].y) * scale;
            if (tmask[tq * 9 + tk]) d = -1e9f;
            scr[tk] = d;
            m = fmaxf(m, d);
        }
        float den = 0.f;
        float2 o = make_float2(0.f, 0.f);
#pragma unroll
        for (int tk = 0; tk < 9; tk++) {
            float e = __expf(scr[tk] - m);
            den += e;
            float2 vf = __half22float2(*(const __half2*)&v[tk]);
            o.x += e * vf.x;
            o.y += e * vf.y;
        }
        float inv = 1.f / den;
        size_t orow = (size_t)(b * 9 + tq) * 1024 + hw;
        __half2 ho = __floats2half2_rn(o.x * inv, o.y * inv);
        *((__half2*)(g_ao + orow * 256 + head * 32) + hl) = ho;
    }
}

// ---------------- CLS frame spatial mean + broadcast ----------------
__global__ void cls_avg()
{
    int b = blockIdx.x;
    int d = blockIdx.y * 32 + (threadIdx.x & 31);
    int part = threadIdx.x >> 5;
    float s = 0.f;
    for (int hw = part; hw < 1024; hw += 8)
        s += g_x2[(((size_t)b * 9) * 1024 + hw) * 256 + d];
    __shared__ float sm[8][32];
    sm[part][threadIdx.x & 31] = s;
    __syncthreads();
    if (part == 0) {
        float tot = 0.f;
#pragma unroll
        for (int p = 0; p < 8; p++) tot += sm[p][threadIdx.x & 31];
        sm[0][threadIdx.x & 31] = tot * (1.f / 1024.f);
    }
    __syncthreads();
    float avg = sm[0][threadIdx.x & 31];
    for (int hw = part; hw < 1024; hw += 8)
        g_x2[(((size_t)b * 9) * 1024 + hw) * 256 + d] = avg;
}

// ---------------- launch ----------------
extern "C" void kernel_launch(void* const* d_in, const int* in_sizes, int n_in,
                              void* d_out, int out_size)
{
    const float* query = (const float*)d_in[0];
    const unsigned char* tmask = (const unsigned char*)d_in[2];
    const float* sln_g = (const float*)d_in[3];
    const float* sln_b = (const float*)d_in[4];
    const float* s_wq = (const float*)d_in[5];
    const float* s_bq = (const float*)d_in[6];
    const float* s_wk = (const float*)d_in[7];
    const float* s_bk = (const float*)d_in[8];
    const float* s_wv = (const float*)d_in[9];
    const float* s_bv = (const float*)d_in[10];
    const float* s_wo = (const float*)d_in[11];
    const float* s_bo = (const float*)d_in[12];
    const float* tln_g = (const float*)d_in[13];
    const float* tln_b = (const float*)d_in[14];
    const float* t_wq = (const float*)d_in[15];
    const float* t_bq = (const float*)d_in[16];
    const float* t_wk = (const float*)d_in[17];
    const float* t_bk = (const float*)d_in[18];
    const float* t_wv = (const float*)d_in[19];
    const float* t_bv = (const float*)d_in[20];
    const float* t_wo = (const float*)d_in[21];
    const float* t_bo = (const float*)d_in[22];
    const float* mln_g = (const float*)d_in[23];
    const float* mln_b = (const float*)d_in[24];
    const float* w1 = (const float*)d_in[25];
    const float* b1 = (const float*)d_in[26];
    const float* w2 = (const float*)d_in[27];
    const float* b2 = (const float*)d_in[28];
    float* out = (float*)d_out;

    __half *p_ln, *p_ao, *p_h, *p_qkv, *p_wqkvT, *p_wqkvT2, *p_wT1, *p_wT2, *p_w1T, *p_w2T;
    float *p_x, *p_x2, *p_bqkv, *p_bqkv2;
    cudaGetSymbolAddress((void**)&p_ln, g_ln);
    cudaGetSymbolAddress((void**)&p_qkv, g_qkv);
    cudaGetSymbolAddress((void**)&p_ao, g_ao);
    cudaGetSymbolAddress((void**)&p_x, g_x);
    cudaGetSymbolAddress((void**)&p_x2, g_x2);
    cudaGetSymbolAddress((void**)&p_h, g_h);
    cudaGetSymbolAddress((void**)&p_wqkvT, g_wqkvT);
    cudaGetSymbolAddress((void**)&p_wqkvT2, g_wqkvT2);
    cudaGetSymbolAddress((void**)&p_bqkv, g_bqkv);
    cudaGetSymbolAddress((void**)&p_bqkv2, g_bqkv2);
    cudaGetSymbolAddress((void**)&p_wT1, g_wT1);
    cudaGetSymbolAddress((void**)&p_wT2, g_wT2);
    cudaGetSymbolAddress((void**)&p_w1T, g_w1T);
    cudaGetSymbolAddress((void**)&p_w2T, g_w2T);

    cudaFuncSetAttribute(mma_gemm, cudaFuncAttributeMaxDynamicSharedMemorySize, GSMEM_BYTES);

    const int NOG = 1 << 30;

    // ---- weight prep ----
    prep_weights<<<4096, 256>>>(s_wq, s_wk, s_wv, s_bq, s_bk, s_bv,
                                t_wq, t_wk, t_wv, t_bq, t_bk, t_bv,
                                s_wo, t_wo, w1, w2);

    // ---- spatial stage ----
    ln_kernel<<<ROWS_SP / 4, 128>>>(query, sln_g, sln_b, p_ln, ROWS_SP, 8192, 1024);
    mma_gemm<<<dim3(6, ROWS_SP / 128), 256, GSMEM_BYTES>>>(p_ln, p_wqkvT, p_bqkv, nullptr,
            nullptr, p_qkv, ROWS_SP, 768, 256, 4, NOG, 0);
    spatial_attn<<<ROWS_SP * 8 / 256, 256>>>();
    mma_gemm<<<dim3(2, ROWS_SP / 128), 256, GSMEM_BYTES>>>(p_ao, p_wT1, s_bo, query,
            p_x, nullptr, ROWS_SP, 256, 256, 1, 8192, 1024);
    copy_frame8<<<4096, 256>>>(query);

    // ---- temporal stage ----
    ln_kernel<<<ROWS_T / 4, 128>>>(p_x, tln_g, tln_b, p_ln, ROWS_T, NOG, 0);
    mma_gemm<<<dim3(6, ROWS_T / 128), 256, GSMEM_BYTES>>>(p_ln, p_wqkvT2, p_bqkv2, nullptr,
            nullptr, p_qkv, ROWS_T, 768, 256, 4, NOG, 0);
    temporal_attn<<<Bq * HWc, 128>>>(tmask);
    mma_gemm<<<dim3(2, ROWS_T / 128), 256, GSMEM_BYTES>>>(p_ao, p_wT2, t_bo, p_x,
            p_x2, nullptr, ROWS_T, 256, 256, 1, NOG, 0);
    cls_avg<<<dim3(4, 8), 256>>>();

    // ---- MLP stage ----
    ln_kernel<<<ROWS_T / 4, 128>>>(p_x2, mln_g, mln_b, p_ln, ROWS_T, NOG, 0);
    mma_gemm<<<dim3(8, ROWS_T / 128), 256, GSMEM_BYTES>>>(p_ln, p_w1T, b1, nullptr,
            nullptr, p_h, ROWS_T, MLPD, 256, 2 | 4, NOG, 0);
    mma_gemm<<<dim3(2, ROWS_T / 128), 256, GSMEM_BYTES>>>(p_h, p_w2T, b2, p_x2,
            out, nullptr, ROWS_T, 256, 1024, 1, NOG, 0);
}

// round 15
// speedup vs baseline: 4.6472x; 1.0329x over previous
#include <cuda_runtime.h>
#include <cuda_fp16.h>
#include <math.h>
#include <stdint.h>

#define Bq 4
#define Tt 8
#define TQn 9
#define HWc 1024
#define Dm 256
#define MLPD 1024
#define ROWS_SP (Bq*Tt*HWc)   /* 32768 */
#define ROWS_T  (Bq*TQn*HWc)  /* 36864 */

// ---------------- scratch ----------------
__device__ __half g_ln  [(size_t)ROWS_T * Dm];
__device__ __half g_qkv [(size_t)ROWS_T * 768];
__device__ __half g_ao  [(size_t)ROWS_T * Dm];
__device__ float  g_x   [(size_t)ROWS_T * Dm];
__device__ float  g_x2  [(size_t)ROWS_T * Dm];
__device__ __half g_h   [(size_t)ROWS_T * MLPD];
__device__ __half g_wqkvT [768 * 256];
__device__ __half g_wqkvT2[768 * 256];
__device__ float  g_bqkv [768];
__device__ float  g_bqkv2[768];
__device__ __half g_wT1[256 * 256];
__device__ __half g_wT2[256 * 256];
__device__ __half g_w1T[1024 * 256];
__device__ __half g_w2T[256 * 1024];

// ---------------- helpers ----------------
__device__ __forceinline__ float wsum(float v) {
#pragma unroll
    for (int o = 16; o; o >>= 1) v += __shfl_xor_sync(0xffffffffu, v, o);
    return v;
}
__device__ __forceinline__ float hsum16(float v) {
#pragma unroll
    for (int o = 8; o; o >>= 1) v += __shfl_xor_sync(0xffffffffu, v, o);
    return v;
}
__device__ __forceinline__ uint32_t smem_u32(const void* p) {
    uint32_t a;
    asm("{ .reg .u64 t; cvta.to.shared.u64 t, %1; cvt.u32.u64 %0, t; }" : "=r"(a) : "l"(p));
    return a;
}
#define CP_ASYNC16(dst, src) \
    asm volatile("cp.async.cg.shared.global [%0], [%1], 16;" :: "r"(dst), "l"(src))
#define CP_COMMIT() asm volatile("cp.async.commit_group;")
#define CP_WAIT0()  asm volatile("cp.async.wait_group 0;")
#define CP_WAIT1()  asm volatile("cp.async.wait_group 1;")

__device__ __forceinline__ void ldm_x4(uint32_t* r, uint32_t addr) {
    asm volatile("ldmatrix.sync.aligned.m8n8.x4.shared.b16 {%0,%1,%2,%3}, [%4];"
                 : "=r"(r[0]), "=r"(r[1]), "=r"(r[2]), "=r"(r[3]) : "r"(addr));
}
__device__ __forceinline__ void mma_f16(float* c, const uint32_t* a,
                                        uint32_t b0, uint32_t b1) {
    asm volatile(
        "mma.sync.aligned.m16n8k16.row.col.f32.f16.f16.f32 "
        "{%0,%1,%2,%3}, {%4,%5,%6,%7}, {%8,%9}, {%0,%1,%2,%3};"
        : "+f"(c[0]), "+f"(c[1]), "+f"(c[2]), "+f"(c[3])
        : "r"(a[0]), "r"(a[1]), "r"(a[2]), "r"(a[3]), "r"(b0), "r"(b1));
}
__device__ __forceinline__ __half2 u2h2(uint32_t u) { return *(__half2*)&u; }

// ---------------- one-shot weight prep ----------------
__global__ void prep_weights(
    const float* __restrict__ s_wq, const float* __restrict__ s_wk,
    const float* __restrict__ s_wv, const float* __restrict__ s_bq,
    const float* __restrict__ s_bk, const float* __restrict__ s_bv,
    const float* __restrict__ t_wq, const float* __restrict__ t_wk,
    const float* __restrict__ t_wv, const float* __restrict__ t_bq,
    const float* __restrict__ t_bk, const float* __restrict__ t_bv,
    const float* __restrict__ s_wo, const float* __restrict__ t_wo,
    const float* __restrict__ w1,   const float* __restrict__ w2)
{
    int blk = blockIdx.x;
    int tid = threadIdx.x;
    if (blk < 768) {
        int i = blk * 256 + tid;
        int n = i >> 8, k = i & 255;
        const float* w = (n < 256) ? s_wq : (n < 512) ? s_wk : s_wv;
        g_wqkvT[i] = __float2half(w[k * 256 + (n & 255)]);
        if (i < 768)
            g_bqkv[i] = (i < 256) ? s_bq[i] : (i < 512) ? s_bk[i - 256] : s_bv[i - 512];
    } else if (blk < 1536) {
        int i = (blk - 768) * 256 + tid;
        int n = i >> 8, k = i & 255;
        const float* w = (n < 256) ? t_wq : (n < 512) ? t_wk : t_wv;
        g_wqkvT2[i] = __float2half(w[k * 256 + (n & 255)]);
        if (i < 768)
            g_bqkv2[i] = (i < 256) ? t_bq[i] : (i < 512) ? t_bk[i - 256] : t_bv[i - 512];
    } else if (blk < 1792) {
        int i = (blk - 1536) * 256 + tid;
        int n = i >> 8, k = i & 255;
        g_wT1[i] = __float2half(s_wo[k * 256 + n]);
    } else if (blk < 2048) {
        int i = (blk - 1792) * 256 + tid;
        int n = i >> 8, k = i & 255;
        g_wT2[i] = __float2half(t_wo[k * 256 + n]);
    } else if (blk < 3072) {
        int i = (blk - 2048) * 256 + tid;
        int n = i >> 8, k = i & 255;
        g_w1T[i] = __float2half(w1[k * 1024 + n]);
    } else {
        int i = (blk - 3072) * 256 + tid;
        int n = i >> 10, k = i & 1023;
        g_w2T[i] = __float2half(w2[k * 256 + n]);
    }
}

// ---------------- LayerNorm: fp32 in -> fp16 out ----------------
__global__ void ln_kernel(const float* __restrict__ X, const float* __restrict__ gam,
                          const float* __restrict__ bet, __half* __restrict__ Y,
                          int nrows, int grp, int skip)
{
    int row = blockIdx.x * 4 + (threadIdx.x >> 5);
    if (row >= nrows) return;
    int l = threadIdx.x & 31;
    size_t src = ((size_t)row + (size_t)(row / grp) * skip) * Dm;
    float4 v0 = *(const float4*)(X + src + 4 * l);
    float4 v1 = *(const float4*)(X + src + 128 + 4 * l);
    float s  = v0.x + v0.y + v0.z + v0.w + v1.x + v1.y + v1.z + v1.w;
    float sq = v0.x*v0.x + v0.y*v0.y + v0.z*v0.z + v0.w*v0.w
             + v1.x*v1.x + v1.y*v1.y + v1.z*v1.z + v1.w*v1.w;
    s = wsum(s); sq = wsum(sq);
    float mean = s * (1.f / 256.f);
    float var  = sq * (1.f / 256.f) - mean * mean;
    float rstd = rsqrtf(var + 1e-5f);
    float4 ga0 = *(const float4*)(gam + 4 * l), ga1 = *(const float4*)(gam + 128 + 4 * l);
    float4 be0 = *(const float4*)(bet + 4 * l), be1 = *(const float4*)(bet + 128 + 4 * l);
    __half2 h0 = __floats2half2_rn((v0.x - mean) * rstd * ga0.x + be0.x,
                                   (v0.y - mean) * rstd * ga0.y + be0.y);
    __half2 h1 = __floats2half2_rn((v0.z - mean) * rstd * ga0.z + be0.z,
                                   (v0.w - mean) * rstd * ga0.w + be0.w);
    __half2 h2 = __floats2half2_rn((v1.x - mean) * rstd * ga1.x + be1.x,
                                   (v1.y - mean) * rstd * ga1.y + be1.y);
    __half2 h3 = __floats2half2_rn((v1.z - mean) * rstd * ga1.z + be1.z,
                                   (v1.w - mean) * rstd * ga1.w + be1.w);
    uint2 u0 = { *(uint32_t*)&h0, *(uint32_t*)&h1 };
    uint2 u1 = { *(uint32_t*)&h2, *(uint32_t*)&h3 };
    *(uint2*)(Y + (size_t)row * Dm + 4 * l)       = u0;
    *(uint2*)(Y + (size_t)row * Dm + 128 + 4 * l) = u1;
}

// ---------------- fp16 mma.sync GEMM: CTA 128x128, warp 64x32, 3-stage, 2 CTA/SM -----------
#define ARS 80
#define A_BYTES (128 * ARS)
#define B_BYTES (128 * ARS)
#define STAGE_B (A_BYTES + B_BYTES)
#define GSMEM_BYTES (3 * STAGE_B)

__global__ __launch_bounds__(256, 2) void mma_gemm(
    const __half* __restrict__ A, const __half* __restrict__ BT,
    const float* __restrict__ bias, const float* __restrict__ res,
    float* __restrict__ C, __half* __restrict__ Ch,
    int M, int N, int K, int epi, int grp, int skip)
{
    extern __shared__ char smem[];
    uint32_t sbase = smem_u32(smem);

    int tid = threadIdx.x;
    int wid = tid >> 5, lane = tid & 31;
    int wm = wid >> 2, wn = wid & 3;
    int gid = lane >> 2, tig = lane & 3;
    int i8 = lane & 7, bit0 = (lane >> 3) & 1, bit1 = lane >> 4;
    int bx = blockIdx.x, by = blockIdx.y;

    const __half* Abase = A  + (size_t)(by * 128) * K;
    const __half* Bbase = BT + (size_t)(bx * 128) * K;
    int nch = K >> 5;

    float acc[4][4][4];
#pragma unroll
    for (int i = 0; i < 4; i++)
#pragma unroll
        for (int j = 0; j < 4; j++)
#pragma unroll
            for (int c = 0; c < 4; c++) acc[i][j][c] = 0.f;

#pragma unroll
    for (int p = 0; p < 2; p++) {
        uint32_t stA = sbase + p * STAGE_B;
        uint32_t stB = stA + A_BYTES;
        const __half* Ag = Abase + p * 32;
        const __half* Bg = Bbase + p * 32;
#pragma unroll
        for (int i = 0; i < 2; i++) {
            int id = tid + i * 256, row = id >> 2, q = id & 3;
            CP_ASYNC16(stA + row * ARS + q * 16, Ag + (size_t)row * K + q * 8);
            CP_ASYNC16(stB + row * ARS + q * 16, Bg + (size_t)row * K + q * 8);
        }
        CP_COMMIT();
    }

    uint32_t aOff = (uint32_t)((wm * 64 + bit0 * 8 + i8) * ARS + bit1 * 16);
    uint32_t bOff = (uint32_t)(A_BYTES + (wn * 32 + bit1 * 8 + i8) * ARS + bit0 * 16);

    int st = 0;
    for (int ch = 0; ch < nch; ch++) {
        if (ch + 1 < nch) CP_WAIT1(); else CP_WAIT0();
        __syncthreads();
        if (ch + 2 < nch) {
            int ps = st + 2; if (ps >= 3) ps -= 3;
            uint32_t stA = sbase + ps * STAGE_B;
            uint32_t stB = stA + A_BYTES;
            const __half* Ag = Abase + (ch + 2) * 32;
            const __half* Bg = Bbase + (ch + 2) * 32;
#pragma unroll
            for (int i = 0; i < 2; i++) {
                int id = tid + i * 256, row = id >> 2, q = id & 3;
                CP_ASYNC16(stA + row * ARS + q * 16, Ag + (size_t)row * K + q * 8);
                CP_ASYNC16(stB + row * ARS + q * 16, Bg + (size_t)row * K + q * 8);
            }
            CP_COMMIT();
        }
        uint32_t stg = sbase + st * STAGE_B;
#pragma unroll
        for (int k16 = 0; k16 < 2; k16++) {
            uint32_t af[4][4], bf[2][4];
            uint32_t aA = stg + aOff + k16 * 32;
            uint32_t bA = stg + bOff + k16 * 32;
#pragma unroll
            for (int mt = 0; mt < 4; mt++) ldm_x4(af[mt], aA + mt * (16 * ARS));
#pragma unroll
            for (int p = 0; p < 2; p++)   ldm_x4(bf[p], bA + p * (16 * ARS));
#pragma unroll
            for (int mt = 0; mt < 4; mt++)
#pragma unroll
                for (int p = 0; p < 2; p++) {
                    mma_f16(acc[mt][2 * p],     af[mt], bf[p][0], bf[p][1]);
                    mma_f16(acc[mt][2 * p + 1], af[mt], bf[p][2], bf[p][3]);
                }
        }
        st++; if (st == 3) st = 0;
    }

    // ---- epilogue ----
#pragma unroll
    for (int mt = 0; mt < 4; mt++) {
#pragma unroll
        for (int half = 0; half < 2; half++) {
            int row = by * 128 + wm * 64 + mt * 16 + gid + half * 8;
            size_t crow = (size_t)row + (size_t)(row / grp) * skip;
#pragma unroll
            for (int n8 = 0; n8 < 4; n8++) {
                int cc = bx * 128 + wn * 32 + n8 * 8 + 2 * tig;
                float2 v;
                v.x = acc[mt][n8][2 * half + 0] + bias[cc];
                v.y = acc[mt][n8][2 * half + 1] + bias[cc + 1];
                size_t base = crow * (size_t)N + cc;
                if (epi & 1) {
                    float2 rr = *(const float2*)(res + base);
                    v.x += rr.x; v.y += rr.y;
                }
                if (epi & 2) {
                    v.x = 0.5f * v.x * (1.0f + erff(v.x * 0.7071067811865476f));
                    v.y = 0.5f * v.y * (1.0f + erff(v.y * 0.7071067811865476f));
                }
                if (epi & 4) {
                    __half2 h = __floats2half2_rn(v.x, v.y);
                    *(__half2*)(Ch + base) = h;
                } else {
                    *(float2*)(C + base) = v;
                }
            }
        }
    }
}

// ---------------- spatial 3x3 windowed attention: smem-tiled, CTA = one image row ----------
// 256 threads: warp = head, lane = token x. K/V for rows y-1..y+1 staged in smem.
// Smem: K region then V region; token segment = 264 halfs (256 data + 8 pad)
//  -> token stride 528B = 132 words == 4 (mod 32) banks: conflict-free for lane=token.
#define SA_PT   264
#define SA_VOFF (96 * SA_PT)                 /* 3 rows x 32 tokens segments */
#define SA_SMEM (192 * SA_PT * 2)            /* 101376 bytes */

__global__ __launch_bounds__(256) void spatial_attn()
{
    extern __shared__ __half sm[];
    int blk = blockIdx.x;                    // 0..1023 : image-row
    int bt = blk >> 5, y = blk & 31;
    int tid = threadIdx.x;
    int h = tid >> 5;                        // warp = head
    int tok = tid & 31;                      // lane = token x
    const float scale = 0.17677669529663687f;

    // ---- stage K,V for rows y-1..y+1 (clamped; invalid rows masked later) ----
#pragma unroll
    for (int i = 0; i < 24; i++) {
        int idx = i * 256 + tid;             // 0..6143 uint4s
        int kv = (idx >= 3072) ? 1 : 0;
        int rem = idx - kv * 3072;
        int row = rem >> 10;                 // 0..2
        int rem2 = rem & 1023;
        int tokg = rem2 >> 5;
        int u = rem2 & 31;
        int gr = y + row - 1;
        if ((unsigned)gr >= 32u) gr = y;
        int r = (bt << 10) + (gr << 5) + tokg;
        const uint4* src = (const uint4*)(g_qkv + (size_t)r * 768 + 256 + (kv << 8)) + u;
        __half* dst = sm + kv * SA_VOFF + (row * 32 + tokg) * SA_PT + u * 8;
        *(uint4*)dst = *src;
    }
    __syncthreads();

    // ---- per-(token, head) attention ----
    int r = (bt << 10) + (y << 5) + tok;
    const uint4* qp = (const uint4*)(g_qkv + (size_t)r * 768 + h * 32);
    uint4 qv[4];
#pragma unroll
    for (int i = 0; i < 4; i++) qv[i] = qp[i];

    float sc[9];
    int seg9[9];
#pragma unroll
    for (int kk = 0; kk < 9; kk++) {
        int dy = kk / 3 - 1, dx = kk % 3 - 1;
        int ny = y + dy, nx = tok + dx;
        bool valid = ((unsigned)ny < 32u) && ((unsigned)nx < 32u);
        int nxc = valid ? nx : tok;
        int seg = ((dy + 1) * 32 + nxc) * SA_PT + h * 32;
        seg9[kk] = seg;
        const uint4* kp = (const uint4*)(sm + seg);
        float d = 0.f;
#pragma unroll
        for (int i = 0; i < 4; i++) {
            uint4 kvv = kp[i];
            __half2 a = __hmul2(u2h2(qv[i].x), u2h2(kvv.x));
            a = __hfma2(u2h2(qv[i].y), u2h2(kvv.y), a);
            a = __hfma2(u2h2(qv[i].z), u2h2(kvv.z), a);
            a = __hfma2(u2h2(qv[i].w), u2h2(kvv.w), a);
            float2 f = __half22float2(a);
            d += f.x + f.y;
        }
        sc[kk] = valid ? d * scale : -1e30f;
    }
    float m = sc[0];
#pragma unroll
    for (int kk = 1; kk < 9; kk++) m = fmaxf(m, sc[kk]);

    __half2 o[16];
#pragma unroll
    for (int i = 0; i < 16; i++) o[i] = __float2half2_rn(0.f);
    float den = 0.f;
#pragma unroll
    for (int kk = 0; kk < 9; kk++) {
        float e = __expf(sc[kk] - m);
        den += e;
        __half2 e2 = __float2half2_rn(e);
        const uint4* vp = (const uint4*)(sm + SA_VOFF + seg9[kk]);
#pragma unroll
        for (int i = 0; i < 4; i++) {
            uint4 vvv = vp[i];
            o[4 * i + 0] = __hfma2(e2, u2h2(vvv.x), o[4 * i + 0]);
            o[4 * i + 1] = __hfma2(e2, u2h2(vvv.y), o[4 * i + 1]);
            o[4 * i + 2] = __hfma2(e2, u2h2(vvv.z), o[4 * i + 2]);
            o[4 * i + 3] = __hfma2(e2, u2h2(vvv.w), o[4 * i + 3]);
        }
    }
    float inv = 1.f / den;
    uint4* op = (uint4*)(g_ao + (size_t)r * 256 + h * 32);
#pragma unroll
    for (int i = 0; i < 4; i++) {
        uint4 outv;
        uint32_t* w = &outv.x;
#pragma unroll
        for (int j = 0; j < 4; j++) {
            float2 f = __half22float2(o[4 * i + j]);
            __half2 hh = __floats2half2_rn(f.x * inv, f.y * inv);
            w[j] = *(uint32_t*)&hh;
        }
        op[i] = outv;
    }
}

// ---------------- copy frame-8 query rows into g_x ----------------
__global__ void copy_frame8(const float* __restrict__ query)
{
    int blk = blockIdx.x;
    int b = blk >> 10, hw = blk & 1023;
    size_t idx = (((size_t)(b * 9 + 8) << 10) + hw) * 256 + threadIdx.x;
    g_x[idx] = query[idx];
}

// ---------------- temporal RoPE attention: 128 thr/seq, 2 heads/warp ----------
__global__ void temporal_attn(const unsigned char* __restrict__ tmask)
{
    int s = blockIdx.x;
    int w = threadIdx.x >> 5;
    int l = threadIdx.x & 31;
    int head = 2 * w + (l >> 4);
    int hl = l & 15;
    int b = s >> 10, hw = s & 1023;
    const float scale = 0.17677669529663687f;

    int i0 = 2 * (hl & 7), i1 = i0 + 1;
    float f0 = __powf(10000.f, -(float)i0 / 16.f);
    float f1 = __powf(10000.f, -(float)i1 / 16.f);
    bool x1side = (hl < 8);

    float2 q[9], k[9];
    uint32_t v[9];
#pragma unroll
    for (int t = 0; t < 9; t++) {
        size_t base = ((size_t)(b * 9 + t) * 1024 + hw) * 768 + head * 32;
        float2 qv = __half22float2(*((const __half2*)(g_qkv + base) + hl));
        float2 kv = __half22float2(*((const __half2*)(g_qkv + base + 256) + hl));
        v[t] = *(const uint32_t*)((const __half2*)(g_qkv + base + 512) + hl);
        float c0, s0, c1, s1;
        sincosf((float)t * f0, &s0, &c0);
        sincosf((float)t * f1, &s1, &c1);
        float2 qpart, kpart;
        qpart.x = __shfl_xor_sync(0xffffffffu, qv.x, 8);
        qpart.y = __shfl_xor_sync(0xffffffffu, qv.y, 8);
        kpart.x = __shfl_xor_sync(0xffffffffu, kv.x, 8);
        kpart.y = __shfl_xor_sync(0xffffffffu, kv.y, 8);
        if (x1side) {
            q[t].x = qv.x * c0 - qpart.x * s0;
            q[t].y = qv.y * c1 - qpart.y * s1;
            k[t].x = kv.x * c0 - kpart.x * s0;
            k[t].y = kv.y * c1 - kpart.y * s1;
        } else {
            q[t].x = qpart.x * s0 + qv.x * c0;
            q[t].y = qpart.y * s1 + qv.y * c1;
            k[t].x = kpart.x * s0 + kv.x * c0;
            k[t].y = kpart.y * s1 + kv.y * c1;
        }
    }
#pragma unroll
    for (int tq = 0; tq < 9; tq++) {
        float scr[9];
        float m = -1e30f;
#pragma unroll
        for (int tk = 0; tk < 9; tk++) {
            float d = hsum16(q[tq].x * k[tk].x + q[tq].y * k[tk].y) * scale;
            if (tmask[tq * 9 + tk]) d = -1e9f;
            scr[tk] = d;
            m = fmaxf(m, d);
        }
        float den = 0.f;
        float2 o = make_float2(0.f, 0.f);
#pragma unroll
        for (int tk = 0; tk < 9; tk++) {
            float e = __expf(scr[tk] - m);
            den += e;
            float2 vf = __half22float2(*(const __half2*)&v[tk]);
            o.x += e * vf.x;
            o.y += e * vf.y;
        }
        float inv = 1.f / den;
        size_t orow = (size_t)(b * 9 + tq) * 1024 + hw;
        __half2 ho = __floats2half2_rn(o.x * inv, o.y * inv);
        *((__half2*)(g_ao + orow * 256 + head * 32) + hl) = ho;
    }
}

// ---------------- CLS frame spatial mean + broadcast ----------------
__global__ void cls_avg()
{
    int b = blockIdx.x;
    int d = blockIdx.y * 32 + (threadIdx.x & 31);
    int part = threadIdx.x >> 5;
    float s = 0.f;
    for (int hw = part; hw < 1024; hw += 8)
        s += g_x2[(((size_t)b * 9) * 1024 + hw) * 256 + d];
    __shared__ float sm[8][32];
    sm[part][threadIdx.x & 31] = s;
    __syncthreads();
    if (part == 0) {
        float tot = 0.f;
#pragma unroll
        for (int p = 0; p < 8; p++) tot += sm[p][threadIdx.x & 31];
        sm[0][threadIdx.x & 31] = tot * (1.f / 1024.f);
    }
    __syncthreads();
    float avg = sm[0][threadIdx.x & 31];
    for (int hw = part; hw < 1024; hw += 8)
        g_x2[(((size_t)b * 9) * 1024 + hw) * 256 + d] = avg;
}

// ---------------- launch ----------------
extern "C" void kernel_launch(void* const* d_in, const int* in_sizes, int n_in,
                              void* d_out, int out_size)
{
    const float* query = (const float*)d_in[0];
    const unsigned char* tmask = (const unsigned char*)d_in[2];
    const float* sln_g = (const float*)d_in[3];
    const float* sln_b = (const float*)d_in[4];
    const float* s_wq = (const float*)d_in[5];
    const float* s_bq = (const float*)d_in[6];
    const float* s_wk = (const float*)d_in[7];
    const float* s_bk = (const float*)d_in[8];
    const float* s_wv = (const float*)d_in[9];
    const float* s_bv = (const float*)d_in[10];
    const float* s_wo = (const float*)d_in[11];
    const float* s_bo = (const float*)d_in[12];
    const float* tln_g = (const float*)d_in[13];
    const float* tln_b = (const float*)d_in[14];
    const float* t_wq = (const float*)d_in[15];
    const float* t_bq = (const float*)d_in[16];
    const float* t_wk = (const float*)d_in[17];
    const float* t_bk = (const float*)d_in[18];
    const float* t_wv = (const float*)d_in[19];
    const float* t_bv = (const float*)d_in[20];
    const float* t_wo = (const float*)d_in[21];
    const float* t_bo = (const float*)d_in[22];
    const float* mln_g = (const float*)d_in[23];
    const float* mln_b = (const float*)d_in[24];
    const float* w1 = (const float*)d_in[25];
    const float* b1 = (const float*)d_in[26];
    const float* w2 = (const float*)d_in[27];
    const float* b2 = (const float*)d_in[28];
    float* out = (float*)d_out;

    __half *p_ln, *p_ao, *p_h, *p_qkv, *p_wqkvT, *p_wqkvT2, *p_wT1, *p_wT2, *p_w1T, *p_w2T;
    float *p_x, *p_x2, *p_bqkv, *p_bqkv2;
    cudaGetSymbolAddress((void**)&p_ln, g_ln);
    cudaGetSymbolAddress((void**)&p_qkv, g_qkv);
    cudaGetSymbolAddress((void**)&p_ao, g_ao);
    cudaGetSymbolAddress((void**)&p_x, g_x);
    cudaGetSymbolAddress((void**)&p_x2, g_x2);
    cudaGetSymbolAddress((void**)&p_h, g_h);
    cudaGetSymbolAddress((void**)&p_wqkvT, g_wqkvT);
    cudaGetSymbolAddress((void**)&p_wqkvT2, g_wqkvT2);
    cudaGetSymbolAddress((void**)&p_bqkv, g_bqkv);
    cudaGetSymbolAddress((void**)&p_bqkv2, g_bqkv2);
    cudaGetSymbolAddress((void**)&p_wT1, g_wT1);
    cudaGetSymbolAddress((void**)&p_wT2, g_wT2);
    cudaGetSymbolAddress((void**)&p_w1T, g_w1T);
    cudaGetSymbolAddress((void**)&p_w2T, g_w2T);

    cudaFuncSetAttribute(mma_gemm, cudaFuncAttributeMaxDynamicSharedMemorySize, GSMEM_BYTES);
    cudaFuncSetAttribute(spatial_attn, cudaFuncAttributeMaxDynamicSharedMemorySize, SA_SMEM);

    const int NOG = 1 << 30;

    // ---- weight prep ----
    prep_weights<<<4096, 256>>>(s_wq, s_wk, s_wv, s_bq, s_bk, s_bv,
                                t_wq, t_wk, t_wv, t_bq, t_bk, t_bv,
                                s_wo, t_wo, w1, w2);

    // ---- spatial stage ----
    ln_kernel<<<ROWS_SP / 4, 128>>>(query, sln_g, sln_b, p_ln, ROWS_SP, 8192, 1024);
    mma_gemm<<<dim3(6, ROWS_SP / 128), 256, GSMEM_BYTES>>>(p_ln, p_wqkvT, p_bqkv, nullptr,
            nullptr, p_qkv, ROWS_SP, 768, 256, 4, NOG, 0);
    spatial_attn<<<1024, 256, SA_SMEM>>>();
    mma_gemm<<<dim3(2, ROWS_SP / 128), 256, GSMEM_BYTES>>>(p_ao, p_wT1, s_bo, query,
            p_x, nullptr, ROWS_SP, 256, 256, 1, 8192, 1024);
    copy_frame8<<<4096, 256>>>(query);

    // ---- temporal stage ----
    ln_kernel<<<ROWS_T / 4, 128>>>(p_x, tln_g, tln_b, p_ln, ROWS_T, NOG, 0);
    mma_gemm<<<dim3(6, ROWS_T / 128), 256, GSMEM_BYTES>>>(p_ln, p_wqkvT2, p_bqkv2, nullptr,
            nullptr, p_qkv, ROWS_T, 768, 256, 4, NOG, 0);
    temporal_attn<<<Bq * HWc, 128>>>(tmask);
    mma_gemm<<<dim3(2, ROWS_T / 128), 256, GSMEM_BYTES>>>(p_ao, p_wT2, t_bo, p_x,
            p_x2, nullptr, ROWS_T, 256, 256, 1, NOG, 0);
    cls_avg<<<dim3(4, 8), 256>>>();

    // ---- MLP stage ----
    ln_kernel<<<ROWS_T / 4, 128>>>(p_x2, mln_g, mln_b, p_ln, ROWS_T, NOG, 0);
    mma_gemm<<<dim3(8, ROWS_T / 128), 256, GSMEM_BYTES>>>(p_ln, p_w1T, b1, nullptr,
            nullptr, p_h, ROWS_T, MLPD, 256, 2 | 4, NOG, 0);
    mma_gemm<<<dim3(2, ROWS_T / 128), 256, GSMEM_BYTES>>>(p_h, p_w2T, b2, p_x2,
            out, nullptr, ROWS_T, 256, 1024, 1, NOG, 0);
}